// round 3
// baseline (speedup 1.0000x reference)
#include <cuda_runtime.h>
#include <math.h>

// Problem shapes (fixed for this problem instance)
#define DDIM  2048
#define CCLS  1000
#define BATCH 4096
#define NSUP  (CCLS + BATCH)   // 5096
#define CAP   1024             // per-class member list capacity

// ---------------- scratch (static device globals; no runtime allocation) ----------------
__device__ float g_P[(size_t)NSUP * CCLS];     // logits supports @ W^T   (~20.4 MB)
__device__ float g_ent[NSUP];
__device__ int   g_yhat[NSUP];
__device__ float g_invn[NSUP];
__device__ int   g_list[CCLS * CAP];           // per-class member indices (4 MB)
__device__ int   g_mcnt[CCLS];
__device__ float g_Wn[(size_t)CCLS * DDIM];    // normalized class weights (8.2 MB)

// ---------------- SGEMM: C[M,N] = A @ B^T, A rows split across two sources ----------------
// A row r comes from A0 if r < M0 else from A1 (row r - M0). K must be a multiple of 16.
#define BM 128
#define BN 128
#define BK 16

__global__ __launch_bounds__(256, 2)
void sgemm_nt_kernel(const float* __restrict__ A0, int M0,
                     const float* __restrict__ A1,
                     const float* __restrict__ B,
                     float* __restrict__ C,
                     int M, int N, int K)
{
    __shared__ float As[BK][BM + 4];
    __shared__ float Bs[BK][BN + 4];

    const int tid = threadIdx.x;
    const int tx = tid & 15;        // n-dir thread coord
    const int ty = tid >> 4;        // m-dir thread coord
    const int m0 = blockIdx.y * BM;
    const int n0 = blockIdx.x * BN;

    const int lr = tid >> 2;        // 0..63 (row within tile, per load pass)
    const int lc = (tid & 3) << 2;  // 0,4,8,12 (k offset, float4)

    float acc[8][8];
#pragma unroll
    for (int i = 0; i < 8; i++)
#pragma unroll
        for (int j = 0; j < 8; j++) acc[i][j] = 0.f;

    for (int k0 = 0; k0 < K; k0 += BK) {
#pragma unroll
        for (int p = 0; p < 2; ++p) {
            const int r = lr + p * 64;
            const int mrow = m0 + r;
            float4 va = make_float4(0.f, 0.f, 0.f, 0.f);
            if (mrow < M) {
                const float* Ap = (mrow < M0) ? (A0 + (size_t)mrow * K)
                                              : (A1 + (size_t)(mrow - M0) * K);
                va = *reinterpret_cast<const float4*>(Ap + k0 + lc);
            }
            As[lc + 0][r] = va.x; As[lc + 1][r] = va.y;
            As[lc + 2][r] = va.z; As[lc + 3][r] = va.w;

            const int nrow = n0 + r;
            float4 vb = make_float4(0.f, 0.f, 0.f, 0.f);
            if (nrow < N)
                vb = *reinterpret_cast<const float4*>(B + (size_t)nrow * K + k0 + lc);
            Bs[lc + 0][r] = vb.x; Bs[lc + 1][r] = vb.y;
            Bs[lc + 2][r] = vb.z; Bs[lc + 3][r] = vb.w;
        }
        __syncthreads();

#pragma unroll
        for (int kk = 0; kk < BK; ++kk) {
            float a[8], b[8];
            *reinterpret_cast<float4*>(a)     = *reinterpret_cast<const float4*>(&As[kk][ty * 8]);
            *reinterpret_cast<float4*>(a + 4) = *reinterpret_cast<const float4*>(&As[kk][ty * 8 + 4]);
            *reinterpret_cast<float4*>(b)     = *reinterpret_cast<const float4*>(&Bs[kk][tx * 8]);
            *reinterpret_cast<float4*>(b + 4) = *reinterpret_cast<const float4*>(&Bs[kk][tx * 8 + 4]);
#pragma unroll
            for (int i = 0; i < 8; i++)
#pragma unroll
                for (int j = 0; j < 8; j++)
                    acc[i][j] = fmaf(a[i], b[j], acc[i][j]);
        }
        __syncthreads();
    }

#pragma unroll
    for (int i = 0; i < 8; i++) {
        const int m = m0 + ty * 8 + i;
        if (m >= M) continue;
        float* Crow = C + (size_t)m * N;
#pragma unroll
        for (int j = 0; j < 8; j++) {
            const int n = n0 + tx * 8 + j;
            if (n < N) Crow[n] = acc[i][j];
        }
    }
}

// ---------------- entropy + argmax per logits row ----------------
// H = m + log(S) - D/S  with S = sum exp(v-m), D = sum exp(v-m)*v
__global__ void ent_argmax_kernel()
{
    const int r = blockIdx.x;
    const float* row = g_P + (size_t)r * CCLS;
    const int tid = threadIdx.x;

    float lmax = -3.402823466e38f;
    int   lidx = 0x7fffffff;
    for (int j = tid; j < CCLS; j += 256) {
        float v = row[j];
        if (v > lmax) { lmax = v; lidx = j; }   // '>' keeps first occurrence
    }
    __shared__ float sv[256];
    __shared__ int   si[256];
    sv[tid] = lmax; si[tid] = lidx;
    __syncthreads();
    for (int s = 128; s > 0; s >>= 1) {
        if (tid < s) {
            float v2 = sv[tid + s]; int i2 = si[tid + s];
            if (v2 > sv[tid] || (v2 == sv[tid] && i2 < si[tid])) { sv[tid] = v2; si[tid] = i2; }
        }
        __syncthreads();
    }
    const float m = sv[0];
    const int  am = si[0];

    float s = 0.f, d = 0.f;
    for (int j = tid; j < CCLS; j += 256) {
        float v = row[j];
        float e = __expf(v - m);
        s += e; d += e * v;
    }
    __shared__ float ss[256];
    __shared__ float sd[256];
    ss[tid] = s; sd[tid] = d;
    __syncthreads();
    for (int st = 128; st > 0; st >>= 1) {
        if (tid < st) { ss[tid] += ss[tid + st]; sd[tid] += sd[tid + st]; }
        __syncthreads();
    }
    if (tid == 0) {
        float S = ss[0], D = sd[0];
        g_ent[r] = m + logf(S) - D / S;
        g_yhat[r] = am;
    }
}

// ---------------- per-support inverse L2 norm ----------------
__global__ void rownorm_kernel(const float* __restrict__ W, const float* __restrict__ z)
{
    const int r = blockIdx.x;
    const float* row = (r < CCLS) ? (W + (size_t)r * DDIM) : (z + (size_t)(r - CCLS) * DDIM);
    const int tid = threadIdx.x;
    float acc = 0.f;
    for (int j = tid; j < DDIM; j += 256) { float v = row[j]; acc += v * v; }
    __shared__ float sh[256];
    sh[tid] = acc;
    __syncthreads();
    for (int s = 128; s > 0; s >>= 1) {
        if (tid < s) sh[tid] += sh[tid + s];
        __syncthreads();
    }
    if (tid == 0) g_invn[r] = 1.f / fmaxf(sqrtf(sh[0]), 1e-12f);
}

// ---------------- per-class member lists + top-K by entropy (ties: smaller index) ----------------
__global__ void build_lists_kernel(const int* __restrict__ pK)
{
    const int c = blockIdx.x;
    const int lane = threadIdx.x;   // 32 threads
    const int base = c * CAP;
    __shared__ float s_ent[CAP];
    __shared__ unsigned char s_keep[CAP];

    int count = 0;
    for (int n0 = 0; n0 < NSUP; n0 += 32) {
        int n = n0 + lane;
        bool mem = (n < NSUP) && (g_yhat[n] == c);
        unsigned ball = __ballot_sync(0xffffffffu, mem);
        if (mem) {
            int pos = count + __popc(ball & ((1u << lane) - 1u));
            if (pos < CAP) g_list[base + pos] = n;
        }
        count += __popc(ball);
    }
    if (count > CAP) count = CAP;
    const int K = pK[0];

    if (count > K) {
        for (int i = lane; i < count; i += 32) s_ent[i] = g_ent[g_list[base + i]];
        __syncwarp();
        for (int i = lane; i < count; i += 32) {
            float ei = s_ent[i];
            int ni = g_list[base + i];
            int rank = 0;
            for (int j = 0; j < count; j++) {
                float ej = s_ent[j];
                rank += (ej < ei) || (ej == ei && g_list[base + j] < ni);
            }
            s_keep[i] = (rank < K) ? 1 : 0;
        }
        __syncwarp();
        if (lane == 0) {
            int w = 0;
            for (int i = 0; i < count; i++)
                if (s_keep[i]) g_list[base + (w++)] = g_list[base + i];
            g_mcnt[c] = w;     // == K (strict total order via distinct indices)
        }
    } else if (lane == 0) {
        g_mcnt[c] = count;
    }
}

// ---------------- class prototype: sum normalized members, then column-normalize ----------------
__global__ __launch_bounds__(256)
void class_weights_kernel(const float* __restrict__ W, const float* __restrict__ z)
{
    const int c = blockIdx.x;
    const int tid = threadIdx.x;
    float acc[8];
#pragma unroll
    for (int j = 0; j < 8; j++) acc[j] = 0.f;

    const int m = g_mcnt[c];
    const int base = c * CAP;
    for (int i = 0; i < m; i++) {
        const int n = g_list[base + i];
        const float v = g_invn[n];
        const float* row = (n < CCLS) ? (W + (size_t)n * DDIM) : (z + (size_t)(n - CCLS) * DDIM);
#pragma unroll
        for (int j = 0; j < 8; j++) acc[j] += v * row[tid + j * 256];
    }

    float ssq = 0.f;
#pragma unroll
    for (int j = 0; j < 8; j++) ssq += acc[j] * acc[j];
    __shared__ float sh[256];
    sh[tid] = ssq;
    __syncthreads();
    for (int s = 128; s > 0; s >>= 1) {
        if (tid < s) sh[tid] += sh[tid + s];
        __syncthreads();
    }
    __shared__ float s_scale;
    if (tid == 0) s_scale = 1.f / fmaxf(sqrtf(sh[0]), 1e-12f);
    __syncthreads();
    const float sc = s_scale;
#pragma unroll
    for (int j = 0; j < 8; j++)
        g_Wn[(size_t)c * DDIM + tid + j * 256] = acc[j] * sc;
}

// ---------------- launch ----------------
extern "C" void kernel_launch(void* const* d_in, const int* in_sizes, int n_in,
                              void* d_out, int out_size)
{
    const float* z  = (const float*)d_in[0];   // [4096, 2048]
    const float* W  = (const float*)d_in[1];   // [1000, 2048]
    const int*   pK = (const int*)d_in[2];     // scalar filter_K
    float* out = (float*)d_out;                // [4096, 1000]

    void* pP = nullptr;  cudaGetSymbolAddress(&pP, g_P);
    void* pWn = nullptr; cudaGetSymbolAddress(&pWn, g_Wn);

    // 1) P = [W; z] @ W^T   -> [5096, 1000]
    {
        dim3 grid((CCLS + BN - 1) / BN, (NSUP + BM - 1) / BM);
        sgemm_nt_kernel<<<grid, 256>>>(W, CCLS, z, W, (float*)pP, NSUP, CCLS, DDIM);
    }
    // 2) entropy + argmax per support
    ent_argmax_kernel<<<NSUP, 256>>>();
    // 3) inverse norms per support
    rownorm_kernel<<<NSUP, 256>>>(W, z);
    // 4) per-class member lists (+ exact top-K if count > K)
    build_lists_kernel<<<CCLS, 32>>>(pK);
    // 5) normalized class weights [1000, 2048]
    class_weights_kernel<<<CCLS, 256>>>(W, z);
    // 6) out = z @ Wn^T  -> [4096, 1000]
    {
        dim3 grid((CCLS + BN - 1) / BN, (BATCH + BM - 1) / BM);
        sgemm_nt_kernel<<<grid, 256>>>(z, BATCH, z, (const float*)pWn, out, BATCH, CCLS, DDIM);
    }
}

// round 6
// speedup vs baseline: 2.4303x; 2.4303x over previous
#include <cuda_runtime.h>
#include <cuda_bf16.h>
#include <math.h>
#include <stdint.h>

// ---------------- problem shapes ----------------
#define DDIM  2048
#define CCLS  1000
#define BATCH 4096
#define NSUP  (CCLS + BATCH)   // 5096
#define NPAD  5120             // supports padded to multiple of 128
#define BNPAD 1024             // Wn rows padded to multiple of 128
#define CAP   1024

// ---------------- GEMM tiling ----------------
#define BM 128
#define BN 128
#define BK 32
#define NC (DDIM / BK)         // 64 k-chunks
// per stage: A = 128 rows x 128B (hi 64B | lo 64B), B same
#define A_STAGE 16384
#define STAGE_BYTES 32768
#define SMEM_TOTAL (2 * STAGE_BYTES)   // 64 KB

// ---------------- scratch ----------------
__device__ __align__(256) float g_P[(size_t)NSUP * CCLS];
__device__ float g_ent[NSUP];
__device__ int   g_yhat[NSUP];
__device__ float g_invn[NSUP];
__device__ int   g_list[CCLS * CAP];
__device__ int   g_mcnt[CCLS];
__device__ __align__(256) __nv_bfloat16 g_Shi[(size_t)NPAD * DDIM];
__device__ __align__(256) __nv_bfloat16 g_Slo[(size_t)NPAD * DDIM];
__device__ __align__(256) __nv_bfloat16 g_Wnhi[(size_t)BNPAD * DDIM];
__device__ __align__(256) __nv_bfloat16 g_Wnlo[(size_t)BNPAD * DDIM];

// ---------------- PTX helpers (all baseline compute_103-safe) ----------------
__device__ __forceinline__ uint32_t smem_u32(const void* p) {
    uint32_t a;
    asm("{ .reg .u64 t; cvta.to.shared.u64 t, %1; cvt.u32.u64 %0, t; }" : "=r"(a) : "l"(p));
    return a;
}
#define CP_ASYNC16(dst, src) \
    asm volatile("cp.async.cg.shared.global [%0], [%1], 16;" :: "r"(dst), "l"(src) : "memory")
#define CP_COMMIT() asm volatile("cp.async.commit_group;" ::: "memory")
#define CP_WAIT(N)  asm volatile("cp.async.wait_group %0;" :: "n"(N) : "memory")

__device__ __forceinline__ void ldsm4(uint32_t* r, uint32_t addr) {
    asm volatile("ldmatrix.sync.aligned.m8n8.x4.shared.b16 {%0,%1,%2,%3}, [%4];"
                 : "=r"(r[0]), "=r"(r[1]), "=r"(r[2]), "=r"(r[3]) : "r"(addr));
}
__device__ __forceinline__ void mma16816(float* c, const uint32_t* a, uint32_t b0, uint32_t b1) {
    asm volatile("mma.sync.aligned.m16n8k16.row.col.f32.bf16.bf16.f32 "
                 "{%0,%1,%2,%3}, {%4,%5,%6,%7}, {%8,%9}, {%0,%1,%2,%3};"
                 : "+f"(c[0]), "+f"(c[1]), "+f"(c[2]), "+f"(c[3])
                 : "r"(a[0]), "r"(a[1]), "r"(a[2]), "r"(a[3]), "r"(b0), "r"(b1));
}

// ---------------- conversion + row norms ----------------
__global__ __launch_bounds__(256)
void cvt_kernel(const float* __restrict__ W, const float* __restrict__ z)
{
    const int r = blockIdx.x;
    const int tid = threadIdx.x;
    __nv_bfloat16* hi = g_Shi + (size_t)r * DDIM + tid * 8;
    __nv_bfloat16* lo = g_Slo + (size_t)r * DDIM + tid * 8;

    if (r >= NSUP) {
        uint4 zz = make_uint4(0u, 0u, 0u, 0u);
        *reinterpret_cast<uint4*>(hi) = zz;
        *reinterpret_cast<uint4*>(lo) = zz;
        return;
    }
    const float* src = (r < CCLS) ? (W + (size_t)r * DDIM) : (z + (size_t)(r - CCLS) * DDIM);
    const float4* sp = reinterpret_cast<const float4*>(src + tid * 8);
    float4 a = sp[0], b = sp[1];
    float x[8] = {a.x, a.y, a.z, a.w, b.x, b.y, b.z, b.w};

    __nv_bfloat16 h[8], l[8];
    float ssq = 0.f;
#pragma unroll
    for (int j = 0; j < 8; j++) {
        ssq += x[j] * x[j];
        h[j] = __float2bfloat16_rn(x[j]);
        l[j] = __float2bfloat16_rn(x[j] - __bfloat162float(h[j]));
    }
    *reinterpret_cast<uint4*>(hi) = *reinterpret_cast<uint4*>(h);
    *reinterpret_cast<uint4*>(lo) = *reinterpret_cast<uint4*>(l);

    __shared__ float sh[256];
    sh[tid] = ssq;
    __syncthreads();
    for (int s = 128; s > 0; s >>= 1) {
        if (tid < s) sh[tid] += sh[tid + s];
        __syncthreads();
    }
    if (tid == 0) g_invn[r] = 1.f / fmaxf(sqrtf(sh[0]), 1e-12f);
}

// ---------------- bf16x3 GEMM via mma.sync: C[m][n] = sum_k A[m][k]*B[n][k] ----------------
// smem layout per stage: A then B; each: 128 rows x 128 bytes.
// row r: quads q0-3 = hi k-halves (8 bf16 each), q4-7 = lo. phys quad = q ^ (r&7).
__device__ __forceinline__ void load_stage(uint32_t sbase, int stage, int c,
    const __nv_bfloat16* __restrict__ Ahi, const __nv_bfloat16* __restrict__ Alo,
    const __nv_bfloat16* __restrict__ Bhi, const __nv_bfloat16* __restrict__ Blo,
    int m0, int n0, int tid)
{
    const int k0 = c * BK;
    const uint32_t sb = sbase + stage * STAGE_BYTES;
    const int quad = tid & 7;
    const int kq = quad & 3;
#pragma unroll
    for (int p = 0; p < 8; ++p) {
        const int v = p * 256 + tid;                 // 0..2047
        const int row = (v >> 3) & 127;              // v/8 within side
        const bool isB = (v >= 1024);
        const int grow = (isB ? n0 : m0) + row;
        const __nv_bfloat16* src =
            (quad < 4) ? (isB ? Bhi : Ahi) : (isB ? Blo : Alo);
        const __nv_bfloat16* g = src + (size_t)grow * DDIM + k0 + kq * 8;
        const uint32_t dst = sb + (isB ? A_STAGE : 0)
                           + row * 128 + ((quad ^ (row & 7)) * 16);
        CP_ASYNC16(dst, g);
    }
}

__global__ __launch_bounds__(256, 1)
void mma_gemm_kernel(const __nv_bfloat16* __restrict__ Ahi, const __nv_bfloat16* __restrict__ Alo,
                     const __nv_bfloat16* __restrict__ Bhi, const __nv_bfloat16* __restrict__ Blo,
                     float* __restrict__ C, int M)
{
    extern __shared__ __align__(128) char sm[];
    const int tid = threadIdx.x;
    const int wid = tid >> 5;
    const int lane = tid & 31;
    const int wm = wid & 3;        // 4 m-warps x 32 rows
    const int wn = wid >> 2;       // 2 n-warps x 64 cols
    const int m0 = blockIdx.y * BM;
    const int n0 = blockIdx.x * BN;
    const uint32_t sb = smem_u32(sm);

    // ldmatrix lane address pieces
    const int li = lane & 7;
    const int lg = lane >> 3;
    const int rofs = (lg & 1) * 8 + li;   // row within 16-row tile
    const int qofs = lg >> 1;             // 0/1 -> k8 selector within k16

    float acc[2][8][4];
#pragma unroll
    for (int a = 0; a < 2; a++)
#pragma unroll
        for (int b = 0; b < 8; b++)
#pragma unroll
            for (int cc = 0; cc < 4; cc++) acc[a][b][cc] = 0.f;

    load_stage(sb, 0, 0, Ahi, Alo, Bhi, Blo, m0, n0, tid);
    CP_COMMIT();

#pragma unroll 1
    for (int c = 0; c < NC; ++c) {
        const int s = c & 1;
        if (c + 1 < NC) {
            load_stage(sb, 1 - s, c + 1, Ahi, Alo, Bhi, Blo, m0, n0, tid);
            CP_COMMIT();
            CP_WAIT(1);
        } else {
            CP_WAIT(0);
        }
        __syncthreads();

        const uint32_t Ab = sb + s * STAGE_BYTES;
        const uint32_t Bb = Ab + A_STAGE;
#pragma unroll
        for (int ks = 0; ks < 2; ++ks) {
            const int qh = ks * 2 + qofs;       // hi quad
            const int ql = 4 + ks * 2 + qofs;   // lo quad
            uint32_t afh[2][4], afl[2][4];
#pragma unroll
            for (int mt = 0; mt < 2; ++mt) {
                const int r = wm * 32 + mt * 16 + rofs;
                ldsm4(afh[mt], Ab + r * 128 + ((qh ^ (r & 7)) * 16));
                ldsm4(afl[mt], Ab + r * 128 + ((ql ^ (r & 7)) * 16));
            }
#pragma unroll
            for (int ng = 0; ng < 4; ++ng) {
                const int rn = wn * 64 + ng * 16 + rofs;
                uint32_t bfh[4], bfl[4];
                ldsm4(bfh, Bb + rn * 128 + ((qh ^ (rn & 7)) * 16));
                ldsm4(bfl, Bb + rn * 128 + ((ql ^ (rn & 7)) * 16));
#pragma unroll
                for (int mt = 0; mt < 2; ++mt) {
#pragma unroll
                    for (int h = 0; h < 2; ++h) {
                        float* cc = acc[mt][ng * 2 + h];
                        mma16816(cc, afh[mt], bfh[h], bfh[h + 2]);
                        mma16816(cc, afh[mt], bfl[h], bfl[h + 2]);
                        mma16816(cc, afl[mt], bfh[h], bfh[h + 2]);
                    }
                }
            }
        }
        __syncthreads();
    }

    // epilogue
    const int mrow = m0 + wm * 32 + (lane >> 2);
    const int ncol = n0 + wn * 64 + (lane & 3) * 2;
#pragma unroll
    for (int mt = 0; mt < 2; ++mt) {
#pragma unroll
        for (int nt = 0; nt < 8; ++nt) {
            const int m = mrow + mt * 16;
            const int n = ncol + nt * 8;
            float* cc = acc[mt][nt];
            if (n < CCLS) {
                if (m < M)
                    *reinterpret_cast<float2*>(C + (size_t)m * CCLS + n) = make_float2(cc[0], cc[1]);
                if (m + 8 < M)
                    *reinterpret_cast<float2*>(C + (size_t)(m + 8) * CCLS + n) = make_float2(cc[2], cc[3]);
            }
        }
    }
}

// ---------------- entropy + argmax ----------------
__global__ void ent_argmax_kernel()
{
    const int r = blockIdx.x;
    const float* row = g_P + (size_t)r * CCLS;
    const int tid = threadIdx.x;

    float lmax = -3.402823466e38f;
    int   lidx = 0x7fffffff;
    for (int j = tid; j < CCLS; j += 256) {
        float v = row[j];
        if (v > lmax) { lmax = v; lidx = j; }
    }
    __shared__ float sv[256];
    __shared__ int   si[256];
    sv[tid] = lmax; si[tid] = lidx;
    __syncthreads();
    for (int s = 128; s > 0; s >>= 1) {
        if (tid < s) {
            float v2 = sv[tid + s]; int i2 = si[tid + s];
            if (v2 > sv[tid] || (v2 == sv[tid] && i2 < si[tid])) { sv[tid] = v2; si[tid] = i2; }
        }
        __syncthreads();
    }
    const float m = sv[0];
    const int  am = si[0];

    float s = 0.f, d = 0.f;
    for (int j = tid; j < CCLS; j += 256) {
        float v = row[j];
        float e = __expf(v - m);
        s += e; d += e * v;
    }
    __shared__ float ss[256];
    __shared__ float sd[256];
    ss[tid] = s; sd[tid] = d;
    __syncthreads();
    for (int st = 128; st > 0; st >>= 1) {
        if (tid < st) { ss[tid] += ss[tid + st]; sd[tid] += sd[tid + st]; }
        __syncthreads();
    }
    if (tid == 0) {
        float S = ss[0], D = sd[0];
        g_ent[r] = m + logf(S) - D / S;
        g_yhat[r] = am;
    }
}

// ---------------- per-class member lists ----------------
__global__ void build_lists_kernel(const int* __restrict__ pK)
{
    const int c = blockIdx.x;
    const int tid = threadIdx.x;        // 128 threads
    const int wid = tid >> 5;
    const int lane = tid & 31;
    const int base = c * CAP;
    const int per = (NSUP + 3) / 4;
    const int rlo = wid * per;
    const int rhi = min(rlo + per, NSUP);

    __shared__ int wcnt[4];
    __shared__ float s_ent[CAP];
    __shared__ unsigned char s_keep[CAP];

    int cnt = 0;
    for (int n0 = rlo; n0 < rhi; n0 += 32) {
        int n = n0 + lane;
        bool mem = (n < rhi) && (g_yhat[n] == c);
        cnt += __popc(__ballot_sync(0xffffffffu, mem));
    }
    if (lane == 0) wcnt[wid] = cnt;
    __syncthreads();

    int off = 0;
#pragma unroll
    for (int w = 0; w < 4; w++) if (w < wid) off += wcnt[w];
    int total = wcnt[0] + wcnt[1] + wcnt[2] + wcnt[3];

    int pos = off;
    for (int n0 = rlo; n0 < rhi; n0 += 32) {
        int n = n0 + lane;
        bool mem = (n < rhi) && (g_yhat[n] == c);
        unsigned ball = __ballot_sync(0xffffffffu, mem);
        if (mem) {
            int p = pos + __popc(ball & ((1u << lane) - 1u));
            if (p < CAP) g_list[base + p] = n;
        }
        pos += __popc(ball);
    }
    __syncthreads();

    if (total > CAP) total = CAP;
    const int K = pK[0];

    if (total > K) {
        if (wid == 0) {
            for (int i = lane; i < total; i += 32) s_ent[i] = g_ent[g_list[base + i]];
            __syncwarp();
            for (int i = lane; i < total; i += 32) {
                float ei = s_ent[i];
                int ni = g_list[base + i];
                int rank = 0;
                for (int j = 0; j < total; j++) {
                    float ej = s_ent[j];
                    rank += (ej < ei) || (ej == ei && g_list[base + j] < ni);
                }
                s_keep[i] = (rank < K) ? 1 : 0;
            }
            __syncwarp();
            if (lane == 0) {
                int w = 0;
                for (int i = 0; i < total; i++)
                    if (s_keep[i]) g_list[base + (w++)] = g_list[base + i];
                g_mcnt[c] = w;
            }
        }
    } else if (tid == 0) {
        g_mcnt[c] = total;
    }
}

// ---------------- class prototypes -> normalized bf16 hi/lo weights (padded) ----------------
__global__ __launch_bounds__(256)
void class_weights_kernel(const float* __restrict__ W, const float* __restrict__ z)
{
    const int c = blockIdx.x;
    const int tid = threadIdx.x;

    if (c >= CCLS) {    // zero-fill padding rows
        uint4 zz = make_uint4(0u, 0u, 0u, 0u);
        *reinterpret_cast<uint4*>(g_Wnhi + (size_t)c * DDIM + tid * 8) = zz;
        *reinterpret_cast<uint4*>(g_Wnlo + (size_t)c * DDIM + tid * 8) = zz;
        return;
    }

    float acc[8];
#pragma unroll
    for (int j = 0; j < 8; j++) acc[j] = 0.f;

    const int m = g_mcnt[c];
    const int base = c * CAP;
    for (int i = 0; i < m; i++) {
        const int n = g_list[base + i];
        const float v = g_invn[n];
        const float* row = (n < CCLS) ? (W + (size_t)n * DDIM) : (z + (size_t)(n - CCLS) * DDIM);
        const float4* rp = reinterpret_cast<const float4*>(row + tid * 8);
        float4 a = rp[0], b = rp[1];
        acc[0] += v * a.x; acc[1] += v * a.y; acc[2] += v * a.z; acc[3] += v * a.w;
        acc[4] += v * b.x; acc[5] += v * b.y; acc[6] += v * b.z; acc[7] += v * b.w;
    }

    float ssq = 0.f;
#pragma unroll
    for (int j = 0; j < 8; j++) ssq += acc[j] * acc[j];
    __shared__ float sh[256];
    sh[tid] = ssq;
    __syncthreads();
    for (int s = 128; s > 0; s >>= 1) {
        if (tid < s) sh[tid] += sh[tid + s];
        __syncthreads();
    }
    __shared__ float s_scale;
    if (tid == 0) s_scale = 1.f / fmaxf(sqrtf(sh[0]), 1e-12f);
    __syncthreads();
    const float sc = s_scale;

    __nv_bfloat16 h[8], l[8];
#pragma unroll
    for (int j = 0; j < 8; j++) {
        float x = acc[j] * sc;
        h[j] = __float2bfloat16_rn(x);
        l[j] = __float2bfloat16_rn(x - __bfloat162float(h[j]));
    }
    *reinterpret_cast<uint4*>(g_Wnhi + (size_t)c * DDIM + tid * 8) = *reinterpret_cast<uint4*>(h);
    *reinterpret_cast<uint4*>(g_Wnlo + (size_t)c * DDIM + tid * 8) = *reinterpret_cast<uint4*>(l);
}

// ---------------- launch ----------------
extern "C" void kernel_launch(void* const* d_in, const int* in_sizes, int n_in,
                              void* d_out, int out_size)
{
    const float* z  = (const float*)d_in[0];   // [4096, 2048]
    const float* W  = (const float*)d_in[1];   // [1000, 2048]
    const int*   pK = (const int*)d_in[2];     // filter_K
    float* out = (float*)d_out;                // [4096, 1000]

    static bool attr_done = false;
    if (!attr_done) {
        cudaFuncSetAttribute(mma_gemm_kernel, cudaFuncAttributeMaxDynamicSharedMemorySize, SMEM_TOTAL);
        attr_done = true;
    }

    void* pP = nullptr;    cudaGetSymbolAddress(&pP, g_P);
    void* pShi = nullptr;  cudaGetSymbolAddress(&pShi, g_Shi);
    void* pSlo = nullptr;  cudaGetSymbolAddress(&pSlo, g_Slo);
    void* pWnhi = nullptr; cudaGetSymbolAddress(&pWnhi, g_Wnhi);
    void* pWnlo = nullptr; cudaGetSymbolAddress(&pWnlo, g_Wnlo);

    const __nv_bfloat16* Shi = (const __nv_bfloat16*)pShi;
    const __nv_bfloat16* Slo = (const __nv_bfloat16*)pSlo;

    // 1) fp32 -> bf16 hi/lo split of [W; z] (padded) + row inverse norms
    cvt_kernel<<<NPAD, 256>>>(W, z);

    // 2) P = [W; z] @ W^T  (bf16x3 HMMA), [5096, 1000]
    {
        dim3 grid((CCLS + BN - 1) / BN, NPAD / BM);   // 8 x 40
        mma_gemm_kernel<<<grid, 256, SMEM_TOTAL>>>(Shi, Slo, Shi, Slo, (float*)pP, NSUP);
    }
    // 3) entropy + argmax
    ent_argmax_kernel<<<NSUP, 256>>>();
    // 4) per-class lists (+ exact top-K)
    build_lists_kernel<<<CCLS, 128>>>(pK);
    // 5) normalized class prototypes -> bf16 hi/lo (BNPAD rows, padding zeroed)
    class_weights_kernel<<<BNPAD, 256>>>(W, z);
    // 6) out = z @ Wn^T  (bf16x3 HMMA), [4096, 1000]
    {
        dim3 grid((CCLS + BN - 1) / BN, BATCH / BM);  // 8 x 32
        mma_gemm_kernel<<<grid, 256, SMEM_TOTAL>>>(Shi + (size_t)CCLS * DDIM,
                                                   Slo + (size_t)CCLS * DDIM,
                                                   (const __nv_bfloat16*)pWnhi,
                                                   (const __nv_bfloat16*)pWnlo,
                                                   out, BATCH);
    }
}

// round 7
// speedup vs baseline: 2.8062x; 1.1547x over previous
#include <cuda_runtime.h>
#include <cuda_bf16.h>
#include <math.h>
#include <stdint.h>

// ---------------- problem shapes ----------------
#define DDIM  2048
#define CCLS  1000
#define BATCH 4096
#define NSUP  (CCLS + BATCH)   // 5096
#define NPAD  5120             // supports padded to multiple of 128
#define BNPAD 1024             // Wn rows padded to multiple of 128
#define CAP   1024

// ---------------- GEMM tiling ----------------
#define BM 128
#define BN 64
#define BK 32
#define NC (DDIM / BK)         // 64 k-chunks
// per stage: A = 128 rows x 128B (hi 64B | lo 64B), B = 64 rows x 128B
#define A_STAGE 16384
#define STAGE_BYTES 24576
#define NSTAGE 3
#define SMEM_TOTAL (NSTAGE * STAGE_BYTES)   // 73728

// ---------------- scratch ----------------
__device__ __align__(256) float g_P[(size_t)NSUP * CCLS];
__device__ float g_ent[NSUP];
__device__ int   g_yhat[NSUP];
__device__ float g_invn[NSUP];
__device__ int   g_list[CCLS * CAP];
__device__ int   g_mcnt[CCLS];
__device__ __align__(256) __nv_bfloat16 g_Shi[(size_t)NPAD * DDIM];
__device__ __align__(256) __nv_bfloat16 g_Slo[(size_t)NPAD * DDIM];
__device__ __align__(256) __nv_bfloat16 g_Wnhi[(size_t)BNPAD * DDIM];
__device__ __align__(256) __nv_bfloat16 g_Wnlo[(size_t)BNPAD * DDIM];

// ---------------- PTX helpers (baseline compute_103-safe) ----------------
__device__ __forceinline__ uint32_t smem_u32(const void* p) {
    uint32_t a;
    asm("{ .reg .u64 t; cvta.to.shared.u64 t, %1; cvt.u32.u64 %0, t; }" : "=r"(a) : "l"(p));
    return a;
}
#define CP_ASYNC16(dst, src) \
    asm volatile("cp.async.cg.shared.global [%0], [%1], 16;" :: "r"(dst), "l"(src) : "memory")
#define CP_COMMIT() asm volatile("cp.async.commit_group;" ::: "memory")
#define CP_WAIT(N)  asm volatile("cp.async.wait_group %0;" :: "n"(N) : "memory")

__device__ __forceinline__ void ldsm4(uint32_t* r, uint32_t addr) {
    asm volatile("ldmatrix.sync.aligned.m8n8.x4.shared.b16 {%0,%1,%2,%3}, [%4];"
                 : "=r"(r[0]), "=r"(r[1]), "=r"(r[2]), "=r"(r[3]) : "r"(addr));
}
__device__ __forceinline__ void mma16816(float* c, const uint32_t* a, uint32_t b0, uint32_t b1) {
    asm volatile("mma.sync.aligned.m16n8k16.row.col.f32.bf16.bf16.f32 "
                 "{%0,%1,%2,%3}, {%4,%5,%6,%7}, {%8,%9}, {%0,%1,%2,%3};"
                 : "+f"(c[0]), "+f"(c[1]), "+f"(c[2]), "+f"(c[3])
                 : "r"(a[0]), "r"(a[1]), "r"(a[2]), "r"(a[3]), "r"(b0), "r"(b1));
}

// ---------------- conversion + row norms ----------------
__global__ __launch_bounds__(256)
void cvt_kernel(const float* __restrict__ W, const float* __restrict__ z)
{
    const int r = blockIdx.x;
    const int tid = threadIdx.x;
    __nv_bfloat16* hi = g_Shi + (size_t)r * DDIM + tid * 8;
    __nv_bfloat16* lo = g_Slo + (size_t)r * DDIM + tid * 8;

    if (r >= NSUP) {
        uint4 zz = make_uint4(0u, 0u, 0u, 0u);
        *reinterpret_cast<uint4*>(hi) = zz;
        *reinterpret_cast<uint4*>(lo) = zz;
        return;
    }
    const float* src = (r < CCLS) ? (W + (size_t)r * DDIM) : (z + (size_t)(r - CCLS) * DDIM);
    const float4* sp = reinterpret_cast<const float4*>(src + tid * 8);
    float4 a = sp[0], b = sp[1];
    float x[8] = {a.x, a.y, a.z, a.w, b.x, b.y, b.z, b.w};

    __nv_bfloat16 h[8], l[8];
    float ssq = 0.f;
#pragma unroll
    for (int j = 0; j < 8; j++) {
        ssq += x[j] * x[j];
        h[j] = __float2bfloat16_rn(x[j]);
        l[j] = __float2bfloat16_rn(x[j] - __bfloat162float(h[j]));
    }
    *reinterpret_cast<uint4*>(hi) = *reinterpret_cast<uint4*>(h);
    *reinterpret_cast<uint4*>(lo) = *reinterpret_cast<uint4*>(l);

    __shared__ float sh[256];
    sh[tid] = ssq;
    __syncthreads();
    for (int s = 128; s > 0; s >>= 1) {
        if (tid < s) sh[tid] += sh[tid + s];
        __syncthreads();
    }
    if (tid == 0) g_invn[r] = 1.f / fmaxf(sqrtf(sh[0]), 1e-12f);
}

// ---------------- bf16x3 GEMM via mma.sync: C[m][n] = sum_k A[m][k]*B[n][k] ----------------
// smem per stage: A (128 rows x 128B) then B (64 rows x 128B).
// row r: quads 0-3 = hi k-halves (8 bf16 each), 4-7 = lo. phys quad = q ^ (r&7).
__device__ __forceinline__ void load_stage(uint32_t sbase, int stage, int c,
    const __nv_bfloat16* __restrict__ Ahi, const __nv_bfloat16* __restrict__ Alo,
    const __nv_bfloat16* __restrict__ Bhi, const __nv_bfloat16* __restrict__ Blo,
    int m0, int n0, int tid)
{
    const int k0 = c * BK;
    const uint32_t sb = sbase + stage * STAGE_BYTES;
    const int quad = tid & 7;
    const int kq = quad & 3;
#pragma unroll
    for (int p = 0; p < 6; ++p) {
        const int v = p * 256 + tid;                 // 0..1535
        const bool isB = (v >= 1024);
        const int row = (isB ? (v - 1024) : v) >> 3;
        const int grow = (isB ? n0 : m0) + row;
        const __nv_bfloat16* src =
            (quad < 4) ? (isB ? Bhi : Ahi) : (isB ? Blo : Alo);
        const __nv_bfloat16* g = src + (size_t)grow * DDIM + k0 + kq * 8;
        const uint32_t dst = sb + (isB ? A_STAGE : 0)
                           + row * 128 + ((quad ^ (row & 7)) * 16);
        CP_ASYNC16(dst, g);
    }
}

__global__ __launch_bounds__(256, 2)
void mma_gemm_kernel(const __nv_bfloat16* __restrict__ Ahi, const __nv_bfloat16* __restrict__ Alo,
                     const __nv_bfloat16* __restrict__ Bhi, const __nv_bfloat16* __restrict__ Blo,
                     float* __restrict__ C, int M)
{
    extern __shared__ __align__(128) char sm[];
    const int tid = threadIdx.x;
    const int wid = tid >> 5;
    const int lane = tid & 31;
    const int wm = wid & 3;        // 4 m-warps x 32 rows
    const int wn = wid >> 2;       // 2 n-warps x 32 cols
    const int m0 = blockIdx.y * BM;
    const int n0 = blockIdx.x * BN;
    const uint32_t sb = smem_u32(sm);

    const int li = lane & 7;
    const int lg = lane >> 3;
    const int rofs = (lg & 1) * 8 + li;   // row within 16-row tile
    const int qofs = lg >> 1;             // k8 selector within k16

    float acc[2][4][4];
#pragma unroll
    for (int a = 0; a < 2; a++)
#pragma unroll
        for (int b = 0; b < 4; b++)
#pragma unroll
            for (int cc = 0; cc < 4; cc++) acc[a][b][cc] = 0.f;

    load_stage(sb, 0, 0, Ahi, Alo, Bhi, Blo, m0, n0, tid);
    CP_COMMIT();
    load_stage(sb, 1, 1, Ahi, Alo, Bhi, Blo, m0, n0, tid);
    CP_COMMIT();

    int s = 0;
#pragma unroll 1
    for (int c = 0; c < NC; ++c) {
        if (c == NC - 1) { CP_WAIT(0); } else { CP_WAIT(1); }
        __syncthreads();
        if (c + 2 < NC) {
            int ns = s + 2; if (ns >= NSTAGE) ns -= NSTAGE;
            load_stage(sb, ns, c + 2, Ahi, Alo, Bhi, Blo, m0, n0, tid);
            CP_COMMIT();
        }

        const uint32_t Ab = sb + s * STAGE_BYTES;
        const uint32_t Bb = Ab + A_STAGE;
#pragma unroll
        for (int ks = 0; ks < 2; ++ks) {
            const int qh = ks * 2 + qofs;
            const int ql = 4 + ks * 2 + qofs;
            uint32_t afh[2][4], afl[2][4];
#pragma unroll
            for (int mt = 0; mt < 2; ++mt) {
                const int r = wm * 32 + mt * 16 + rofs;
                ldsm4(afh[mt], Ab + r * 128 + ((qh ^ (r & 7)) * 16));
                ldsm4(afl[mt], Ab + r * 128 + ((ql ^ (r & 7)) * 16));
            }
#pragma unroll
            for (int ng = 0; ng < 2; ++ng) {
                const int rn = wn * 32 + ng * 16 + rofs;
                uint32_t bfh[4], bfl[4];
                ldsm4(bfh, Bb + rn * 128 + ((qh ^ (rn & 7)) * 16));
                ldsm4(bfl, Bb + rn * 128 + ((ql ^ (rn & 7)) * 16));
#pragma unroll
                for (int mt = 0; mt < 2; ++mt) {
#pragma unroll
                    for (int h = 0; h < 2; ++h) {
                        float* cc = acc[mt][ng * 2 + h];
                        mma16816(cc, afh[mt], bfh[h], bfh[h + 2]);
                        mma16816(cc, afh[mt], bfl[h], bfl[h + 2]);
                        mma16816(cc, afl[mt], bfh[h], bfh[h + 2]);
                    }
                }
            }
        }
        ++s; if (s >= NSTAGE) s = 0;
    }

    // epilogue
    const int mrow = m0 + wm * 32 + (lane >> 2);
    const int ncol = n0 + wn * 32 + (lane & 3) * 2;
#pragma unroll
    for (int mt = 0; mt < 2; ++mt) {
#pragma unroll
        for (int nt = 0; nt < 4; ++nt) {
            const int m = mrow + mt * 16;
            const int n = ncol + nt * 8;
            float* cc = acc[mt][nt];
            if (n < CCLS) {
                if (m < M)
                    *reinterpret_cast<float2*>(C + (size_t)m * CCLS + n) = make_float2(cc[0], cc[1]);
                if (m + 8 < M)
                    *reinterpret_cast<float2*>(C + (size_t)(m + 8) * CCLS + n) = make_float2(cc[2], cc[3]);
            }
        }
    }
}

// ---------------- entropy + argmax (warp-shuffle reductions) ----------------
__global__ __launch_bounds__(256)
void ent_argmax_kernel()
{
    const int r = blockIdx.x;
    const float* row = g_P + (size_t)r * CCLS;
    const int tid = threadIdx.x;
    const int wid = tid >> 5;
    const int lane = tid & 31;

    float lmax = -3.402823466e38f;
    int   lidx = 0x7fffffff;
    for (int j = tid; j < CCLS; j += 256) {
        float v = row[j];
        if (v > lmax) { lmax = v; lidx = j; }
    }
#pragma unroll
    for (int o = 16; o > 0; o >>= 1) {
        float v2 = __shfl_down_sync(0xffffffffu, lmax, o);
        int   i2 = __shfl_down_sync(0xffffffffu, lidx, o);
        if (v2 > lmax || (v2 == lmax && i2 < lidx)) { lmax = v2; lidx = i2; }
    }
    __shared__ float wv[8];
    __shared__ int   wi[8];
    if (lane == 0) { wv[wid] = lmax; wi[wid] = lidx; }
    __syncthreads();
    __shared__ float s_m;
    __shared__ int   s_am;
    if (tid == 0) {
        float bm = wv[0]; int bi = wi[0];
#pragma unroll
        for (int w = 1; w < 8; w++) {
            if (wv[w] > bm || (wv[w] == bm && wi[w] < bi)) { bm = wv[w]; bi = wi[w]; }
        }
        s_m = bm; s_am = bi;
    }
    __syncthreads();
    const float m = s_m;

    float s = 0.f, d = 0.f;
    for (int j = tid; j < CCLS; j += 256) {
        float v = row[j];
        float e = __expf(v - m);
        s += e; d += e * v;
    }
#pragma unroll
    for (int o = 16; o > 0; o >>= 1) {
        s += __shfl_down_sync(0xffffffffu, s, o);
        d += __shfl_down_sync(0xffffffffu, d, o);
    }
    __shared__ float ws[8], wd[8];
    if (lane == 0) { ws[wid] = s; wd[wid] = d; }
    __syncthreads();
    if (tid == 0) {
        float S = 0.f, D = 0.f;
#pragma unroll
        for (int w = 0; w < 8; w++) { S += ws[w]; D += wd[w]; }
        g_ent[r] = m + logf(S) - D / S;
        g_yhat[r] = s_am;
    }
}

// ---------------- per-class member lists ----------------
__global__ void build_lists_kernel(const int* __restrict__ pK)
{
    const int c = blockIdx.x;
    const int tid = threadIdx.x;        // 128 threads
    const int wid = tid >> 5;
    const int lane = tid & 31;
    const int base = c * CAP;
    const int per = (NSUP + 3) / 4;
    const int rlo = wid * per;
    const int rhi = min(rlo + per, NSUP);

    __shared__ int wcnt[4];
    __shared__ float s_ent[CAP];
    __shared__ unsigned char s_keep[CAP];

    int cnt = 0;
    for (int n0 = rlo; n0 < rhi; n0 += 32) {
        int n = n0 + lane;
        bool mem = (n < rhi) && (g_yhat[n] == c);
        cnt += __popc(__ballot_sync(0xffffffffu, mem));
    }
    if (lane == 0) wcnt[wid] = cnt;
    __syncthreads();

    int off = 0;
#pragma unroll
    for (int w = 0; w < 4; w++) if (w < wid) off += wcnt[w];
    int total = wcnt[0] + wcnt[1] + wcnt[2] + wcnt[3];

    int pos = off;
    for (int n0 = rlo; n0 < rhi; n0 += 32) {
        int n = n0 + lane;
        bool mem = (n < rhi) && (g_yhat[n] == c);
        unsigned ball = __ballot_sync(0xffffffffu, mem);
        if (mem) {
            int p = pos + __popc(ball & ((1u << lane) - 1u));
            if (p < CAP) g_list[base + p] = n;
        }
        pos += __popc(ball);
    }
    __syncthreads();

    if (total > CAP) total = CAP;
    const int K = pK[0];

    if (total > K) {
        if (wid == 0) {
            for (int i = lane; i < total; i += 32) s_ent[i] = g_ent[g_list[base + i]];
            __syncwarp();
            for (int i = lane; i < total; i += 32) {
                float ei = s_ent[i];
                int ni = g_list[base + i];
                int rank = 0;
                for (int j = 0; j < total; j++) {
                    float ej = s_ent[j];
                    rank += (ej < ei) || (ej == ei && g_list[base + j] < ni);
                }
                s_keep[i] = (rank < K) ? 1 : 0;
            }
            __syncwarp();
            if (lane == 0) {
                int w = 0;
                for (int i = 0; i < total; i++)
                    if (s_keep[i]) g_list[base + (w++)] = g_list[base + i];
                g_mcnt[c] = w;
            }
        }
    } else if (tid == 0) {
        g_mcnt[c] = total;
    }
}

// ---------------- class prototypes -> normalized bf16 hi/lo weights (padded) ----------------
__global__ __launch_bounds__(256)
void class_weights_kernel(const float* __restrict__ W, const float* __restrict__ z)
{
    const int c = blockIdx.x;
    const int tid = threadIdx.x;

    if (c >= CCLS) {    // zero-fill padding rows
        uint4 zz = make_uint4(0u, 0u, 0u, 0u);
        *reinterpret_cast<uint4*>(g_Wnhi + (size_t)c * DDIM + tid * 8) = zz;
        *reinterpret_cast<uint4*>(g_Wnlo + (size_t)c * DDIM + tid * 8) = zz;
        return;
    }

    float acc[8];
#pragma unroll
    for (int j = 0; j < 8; j++) acc[j] = 0.f;

    const int m = g_mcnt[c];
    const int base = c * CAP;
    for (int i = 0; i < m; i++) {
        const int n = g_list[base + i];
        const float v = g_invn[n];
        const float* row = (n < CCLS) ? (W + (size_t)n * DDIM) : (z + (size_t)(n - CCLS) * DDIM);
        const float4* rp = reinterpret_cast<const float4*>(row + tid * 8);
        float4 a = rp[0], b = rp[1];
        acc[0] += v * a.x; acc[1] += v * a.y; acc[2] += v * a.z; acc[3] += v * a.w;
        acc[4] += v * b.x; acc[5] += v * b.y; acc[6] += v * b.z; acc[7] += v * b.w;
    }

    float ssq = 0.f;
#pragma unroll
    for (int j = 0; j < 8; j++) ssq += acc[j] * acc[j];
    __shared__ float sh[256];
    sh[tid] = ssq;
    __syncthreads();
    for (int s = 128; s > 0; s >>= 1) {
        if (tid < s) sh[tid] += sh[tid + s];
        __syncthreads();
    }
    __shared__ float s_scale;
    if (tid == 0) s_scale = 1.f / fmaxf(sqrtf(sh[0]), 1e-12f);
    __syncthreads();
    const float sc = s_scale;

    __nv_bfloat16 h[8], l[8];
#pragma unroll
    for (int j = 0; j < 8; j++) {
        float x = acc[j] * sc;
        h[j] = __float2bfloat16_rn(x);
        l[j] = __float2bfloat16_rn(x - __bfloat162float(h[j]));
    }
    *reinterpret_cast<uint4*>(g_Wnhi + (size_t)c * DDIM + tid * 8) = *reinterpret_cast<uint4*>(h);
    *reinterpret_cast<uint4*>(g_Wnlo + (size_t)c * DDIM + tid * 8) = *reinterpret_cast<uint4*>(l);
}

// ---------------- launch ----------------
extern "C" void kernel_launch(void* const* d_in, const int* in_sizes, int n_in,
                              void* d_out, int out_size)
{
    const float* z  = (const float*)d_in[0];   // [4096, 2048]
    const float* W  = (const float*)d_in[1];   // [1000, 2048]
    const int*   pK = (const int*)d_in[2];     // filter_K
    float* out = (float*)d_out;                // [4096, 1000]

    static bool attr_done = false;
    if (!attr_done) {
        cudaFuncSetAttribute(mma_gemm_kernel, cudaFuncAttributeMaxDynamicSharedMemorySize, SMEM_TOTAL);
        attr_done = true;
    }

    void* pP = nullptr;    cudaGetSymbolAddress(&pP, g_P);
    void* pShi = nullptr;  cudaGetSymbolAddress(&pShi, g_Shi);
    void* pSlo = nullptr;  cudaGetSymbolAddress(&pSlo, g_Slo);
    void* pWnhi = nullptr; cudaGetSymbolAddress(&pWnhi, g_Wnhi);
    void* pWnlo = nullptr; cudaGetSymbolAddress(&pWnlo, g_Wnlo);

    const __nv_bfloat16* Shi = (const __nv_bfloat16*)pShi;
    const __nv_bfloat16* Slo = (const __nv_bfloat16*)pSlo;

    // 1) fp32 -> bf16 hi/lo split of [W; z] (padded) + row inverse norms
    cvt_kernel<<<NPAD, 256>>>(W, z);

    // 2) P = [W; z] @ W^T  (bf16x3 HMMA), [5096, 1000]
    {
        dim3 grid((CCLS + BN - 1) / BN, NPAD / BM);   // 16 x 40 = 640
        mma_gemm_kernel<<<grid, 256, SMEM_TOTAL>>>(Shi, Slo, Shi, Slo, (float*)pP, NSUP);
    }
    // 3) entropy + argmax
    ent_argmax_kernel<<<NSUP, 256>>>();
    // 4) per-class lists (+ exact top-K)
    build_lists_kernel<<<CCLS, 128>>>(pK);
    // 5) normalized class prototypes -> bf16 hi/lo (BNPAD rows, padding zeroed)
    class_weights_kernel<<<BNPAD, 256>>>(W, z);
    // 6) out = z @ Wn^T  (bf16x3 HMMA), [4096, 1000]
    {
        dim3 grid((CCLS + BN - 1) / BN, BATCH / BM);  // 16 x 32 = 512
        mma_gemm_kernel<<<grid, 256, SMEM_TOTAL>>>(Shi + (size_t)CCLS * DDIM,
                                                   Slo + (size_t)CCLS * DDIM,
                                                   (const __nv_bfloat16*)pWnhi,
                                                   (const __nv_bfloat16*)pWnlo,
                                                   out, BATCH);
    }
}

// round 8
// speedup vs baseline: 2.8888x; 1.0295x over previous
#include <cuda_runtime.h>
#include <cuda_bf16.h>
#include <math.h>
#include <stdint.h>

// ---------------- problem shapes ----------------
#define DDIM  2048
#define CCLS  1000
#define BATCH 4096
#define NSUP  (CCLS + BATCH)   // 5096
#define NPAD  5120             // supports padded to multiple of 128
#define BNPAD 1024             // Wn rows padded to multiple of 128
#define CAP   1024

// ---------------- GEMM tiling ----------------
#define BM 128
#define BN 64
#define BK 32
// per stage: A = 128 rows x 128B (hi 64B | lo 64B), B = 64 rows x 128B
#define A_STAGE 16384
#define STAGE_BYTES 24576
#define NSTAGE 4
#define SMEM_TOTAL (NSTAGE * STAGE_BYTES)   // 98304

// ---------------- scratch ----------------
__device__ __align__(256) float g_P[(size_t)NSUP * CCLS];    // split-K partial 0
__device__ __align__(256) float g_P2[(size_t)NSUP * CCLS];   // split-K partial 1
__device__ float g_ent[NSUP];
__device__ int   g_yhat[NSUP];
__device__ float g_invn[NSUP];
__device__ int   g_list[CCLS * CAP];
__device__ int   g_mcnt[CCLS];
__device__ __align__(256) __nv_bfloat16 g_Shi[(size_t)NPAD * DDIM];
__device__ __align__(256) __nv_bfloat16 g_Slo[(size_t)NPAD * DDIM];
__device__ __align__(256) __nv_bfloat16 g_Wnhi[(size_t)BNPAD * DDIM];
__device__ __align__(256) __nv_bfloat16 g_Wnlo[(size_t)BNPAD * DDIM];

// ---------------- PTX helpers (baseline compute_103-safe) ----------------
__device__ __forceinline__ uint32_t smem_u32(const void* p) {
    uint32_t a;
    asm("{ .reg .u64 t; cvta.to.shared.u64 t, %1; cvt.u32.u64 %0, t; }" : "=r"(a) : "l"(p));
    return a;
}
#define CP_ASYNC16(dst, src) \
    asm volatile("cp.async.cg.shared.global [%0], [%1], 16;" :: "r"(dst), "l"(src) : "memory")
#define CP_COMMIT() asm volatile("cp.async.commit_group;" ::: "memory")
#define CP_WAIT(N)  asm volatile("cp.async.wait_group %0;" :: "n"(N) : "memory")

__device__ __forceinline__ void ldsm4(uint32_t* r, uint32_t addr) {
    asm volatile("ldmatrix.sync.aligned.m8n8.x4.shared.b16 {%0,%1,%2,%3}, [%4];"
                 : "=r"(r[0]), "=r"(r[1]), "=r"(r[2]), "=r"(r[3]) : "r"(addr));
}
__device__ __forceinline__ void mma16816(float* c, const uint32_t* a, uint32_t b0, uint32_t b1) {
    asm volatile("mma.sync.aligned.m16n8k16.row.col.f32.bf16.bf16.f32 "
                 "{%0,%1,%2,%3}, {%4,%5,%6,%7}, {%8,%9}, {%0,%1,%2,%3};"
                 : "+f"(c[0]), "+f"(c[1]), "+f"(c[2]), "+f"(c[3])
                 : "r"(a[0]), "r"(a[1]), "r"(a[2]), "r"(a[3]), "r"(b0), "r"(b1));
}

// ---------------- conversion + row norms ----------------
__global__ __launch_bounds__(256)
void cvt_kernel(const float* __restrict__ W, const float* __restrict__ z)
{
    const int r = blockIdx.x;
    const int tid = threadIdx.x;
    __nv_bfloat16* hi = g_Shi + (size_t)r * DDIM + tid * 8;
    __nv_bfloat16* lo = g_Slo + (size_t)r * DDIM + tid * 8;

    if (r >= NSUP) {
        uint4 zz = make_uint4(0u, 0u, 0u, 0u);
        *reinterpret_cast<uint4*>(hi) = zz;
        *reinterpret_cast<uint4*>(lo) = zz;
        return;
    }
    const float* src = (r < CCLS) ? (W + (size_t)r * DDIM) : (z + (size_t)(r - CCLS) * DDIM);
    const float4* sp = reinterpret_cast<const float4*>(src + tid * 8);
    float4 a = sp[0], b = sp[1];
    float x[8] = {a.x, a.y, a.z, a.w, b.x, b.y, b.z, b.w};

    __nv_bfloat16 h[8], l[8];
    float ssq = 0.f;
#pragma unroll
    for (int j = 0; j < 8; j++) {
        ssq += x[j] * x[j];
        h[j] = __float2bfloat16_rn(x[j]);
        l[j] = __float2bfloat16_rn(x[j] - __bfloat162float(h[j]));
    }
    *reinterpret_cast<uint4*>(hi) = *reinterpret_cast<uint4*>(h);
    *reinterpret_cast<uint4*>(lo) = *reinterpret_cast<uint4*>(l);

    __shared__ float sh[256];
    sh[tid] = ssq;
    __syncthreads();
    for (int s = 128; s > 0; s >>= 1) {
        if (tid < s) sh[tid] += sh[tid + s];
        __syncthreads();
    }
    if (tid == 0) g_invn[r] = 1.f / fmaxf(sqrtf(sh[0]), 1e-12f);
}

// ---------------- bf16x3 GEMM via mma.sync: C[m][n] = sum_k A[m][k]*B[n][k] ----------------
// smem per stage: A (128 rows x 128B) then B (64 rows x 128B).
// row r: quads 0-3 = hi k-halves (8 bf16 each), 4-7 = lo. phys quad = q ^ (r&7).
__device__ __forceinline__ void load_stage(uint32_t sbase, int stage, int k0,
    const __nv_bfloat16* __restrict__ Ahi, const __nv_bfloat16* __restrict__ Alo,
    const __nv_bfloat16* __restrict__ Bhi, const __nv_bfloat16* __restrict__ Blo,
    int m0, int n0, int tid)
{
    const uint32_t sb = sbase + stage * STAGE_BYTES;
    const int quad = tid & 7;
    const int kq = quad & 3;
#pragma unroll
    for (int p = 0; p < 6; ++p) {
        const int v = p * 256 + tid;                 // 0..1535
        const bool isB = (v >= 1024);
        const int row = (isB ? (v - 1024) : v) >> 3;
        const int grow = (isB ? n0 : m0) + row;
        const __nv_bfloat16* src =
            (quad < 4) ? (isB ? Bhi : Ahi) : (isB ? Blo : Alo);
        const __nv_bfloat16* g = src + (size_t)grow * DDIM + k0 + kq * 8;
        const uint32_t dst = sb + (isB ? A_STAGE : 0)
                           + row * 128 + ((quad ^ (row & 7)) * 16);
        CP_ASYNC16(dst, g);
    }
}

// kchunks: BK-chunks handled by this CTA; k origin = blockIdx.z * kchunks * BK.
// output buffer: C0 for z==0, C1 for z==1.
__global__ __launch_bounds__(256, 2)
void mma_gemm_kernel(const __nv_bfloat16* __restrict__ Ahi, const __nv_bfloat16* __restrict__ Alo,
                     const __nv_bfloat16* __restrict__ Bhi, const __nv_bfloat16* __restrict__ Blo,
                     float* __restrict__ C0, float* __restrict__ C1,
                     int M, int kchunks)
{
    extern __shared__ __align__(128) char sm[];
    const int tid = threadIdx.x;
    const int wid = tid >> 5;
    const int lane = tid & 31;
    const int wm = wid & 3;        // 4 m-warps x 32 rows
    const int wn = wid >> 2;       // 2 n-warps x 32 cols
    const int m0 = blockIdx.y * BM;
    const int n0 = blockIdx.x * BN;
    const int kb = blockIdx.z * kchunks * BK;
    float* __restrict__ C = blockIdx.z ? C1 : C0;
    const uint32_t sb = smem_u32(sm);

    const int li = lane & 7;
    const int lg = lane >> 3;
    const int rofs = (lg & 1) * 8 + li;   // row within 16-row tile
    const int qofs = lg >> 1;             // k8 selector within k16

    float acc[2][4][4];
#pragma unroll
    for (int a = 0; a < 2; a++)
#pragma unroll
        for (int b = 0; b < 4; b++)
#pragma unroll
            for (int cc = 0; cc < 4; cc++) acc[a][b][cc] = 0.f;

    // prologue: 3 stages in flight
    load_stage(sb, 0, kb, Ahi, Alo, Bhi, Blo, m0, n0, tid);
    CP_COMMIT();
    load_stage(sb, 1, kb + BK, Ahi, Alo, Bhi, Blo, m0, n0, tid);
    CP_COMMIT();
    load_stage(sb, 2, kb + 2 * BK, Ahi, Alo, Bhi, Blo, m0, n0, tid);
    CP_COMMIT();

#pragma unroll 1
    for (int c = 0; c < kchunks; ++c) {
        const int s = c & 3;
        const int rem = kchunks - 1 - c;   // groups committed after chunk c
        if (rem >= 2)      { CP_WAIT(2); }
        else if (rem == 1) { CP_WAIT(1); }
        else               { CP_WAIT(0); }
        __syncthreads();
        if (c + 3 < kchunks) {
            load_stage(sb, (c + 3) & 3, kb + (c + 3) * BK, Ahi, Alo, Bhi, Blo, m0, n0, tid);
            CP_COMMIT();
        }

        const uint32_t Ab = sb + s * STAGE_BYTES;
        const uint32_t Bb = Ab + A_STAGE;
#pragma unroll
        for (int ks = 0; ks < 2; ++ks) {
            const int qh = ks * 2 + qofs;
            const int ql = 4 + ks * 2 + qofs;
            uint32_t afh[2][4], afl[2][4];
#pragma unroll
            for (int mt = 0; mt < 2; ++mt) {
                const int r = wm * 32 + mt * 16 + rofs;
                ldsm4(afh[mt], Ab + r * 128 + ((qh ^ (r & 7)) * 16));
                ldsm4(afl[mt], Ab + r * 128 + ((ql ^ (r & 7)) * 16));
            }
#pragma unroll
            for (int ng = 0; ng < 2; ++ng) {
                const int rn = wn * 32 + ng * 16 + rofs;
                uint32_t bfh[4], bfl[4];
                ldsm4(bfh, Bb + rn * 128 + ((qh ^ (rn & 7)) * 16));
                ldsm4(bfl, Bb + rn * 128 + ((ql ^ (rn & 7)) * 16));
#pragma unroll
                for (int mt = 0; mt < 2; ++mt) {
#pragma unroll
                    for (int h = 0; h < 2; ++h) {
                        float* cc = acc[mt][ng * 2 + h];
                        mma16816(cc, afh[mt], bfh[h], bfh[h + 2]);
                        mma16816(cc, afh[mt], bfl[h], bfl[h + 2]);
                        mma16816(cc, afl[mt], bfh[h], bfh[h + 2]);
                    }
                }
            }
        }
    }

    // epilogue
    const int mrow = m0 + wm * 32 + (lane >> 2);
    const int ncol = n0 + wn * 32 + (lane & 3) * 2;
#pragma unroll
    for (int mt = 0; mt < 2; ++mt) {
#pragma unroll
        for (int nt = 0; nt < 4; ++nt) {
            const int m = mrow + mt * 16;
            const int n = ncol + nt * 8;
            float* cc = acc[mt][nt];
            if (n < CCLS) {
                if (m < M)
                    *reinterpret_cast<float2*>(C + (size_t)m * CCLS + n) = make_float2(cc[0], cc[1]);
                if (m + 8 < M)
                    *reinterpret_cast<float2*>(C + (size_t)(m + 8) * CCLS + n) = make_float2(cc[2], cc[3]);
            }
        }
    }
}

// ---------------- entropy + argmax (sums split-K partials on the fly) ----------------
__global__ __launch_bounds__(256)
void ent_argmax_kernel()
{
    const int r = blockIdx.x;
    const float* row0 = g_P  + (size_t)r * CCLS;
    const float* row1 = g_P2 + (size_t)r * CCLS;
    const int tid = threadIdx.x;
    const int wid = tid >> 5;
    const int lane = tid & 31;

    float lmax = -3.402823466e38f;
    int   lidx = 0x7fffffff;
    for (int j = tid; j < CCLS; j += 256) {
        float v = row0[j] + row1[j];
        if (v > lmax) { lmax = v; lidx = j; }
    }
#pragma unroll
    for (int o = 16; o > 0; o >>= 1) {
        float v2 = __shfl_down_sync(0xffffffffu, lmax, o);
        int   i2 = __shfl_down_sync(0xffffffffu, lidx, o);
        if (v2 > lmax || (v2 == lmax && i2 < lidx)) { lmax = v2; lidx = i2; }
    }
    __shared__ float wv[8];
    __shared__ int   wi[8];
    if (lane == 0) { wv[wid] = lmax; wi[wid] = lidx; }
    __syncthreads();
    __shared__ float s_m;
    __shared__ int   s_am;
    if (tid == 0) {
        float bm = wv[0]; int bi = wi[0];
#pragma unroll
        for (int w = 1; w < 8; w++) {
            if (wv[w] > bm || (wv[w] == bm && wi[w] < bi)) { bm = wv[w]; bi = wi[w]; }
        }
        s_m = bm; s_am = bi;
    }
    __syncthreads();
    const float m = s_m;

    float s = 0.f, d = 0.f;
    for (int j = tid; j < CCLS; j += 256) {
        float v = row0[j] + row1[j];
        float e = __expf(v - m);
        s += e; d += e * v;
    }
#pragma unroll
    for (int o = 16; o > 0; o >>= 1) {
        s += __shfl_down_sync(0xffffffffu, s, o);
        d += __shfl_down_sync(0xffffffffu, d, o);
    }
    __shared__ float ws[8], wd[8];
    if (lane == 0) { ws[wid] = s; wd[wid] = d; }
    __syncthreads();
    if (tid == 0) {
        float S = 0.f, D = 0.f;
#pragma unroll
        for (int w = 0; w < 8; w++) { S += ws[w]; D += wd[w]; }
        g_ent[r] = m + logf(S) - D / S;
        g_yhat[r] = s_am;
    }
}

// ---------------- per-class member lists ----------------
__global__ void build_lists_kernel(const int* __restrict__ pK)
{
    const int c = blockIdx.x;
    const int tid = threadIdx.x;        // 128 threads
    const int wid = tid >> 5;
    const int lane = tid & 31;
    const int base = c * CAP;
    const int per = (NSUP + 3) / 4;
    const int rlo = wid * per;
    const int rhi = min(rlo + per, NSUP);

    __shared__ int wcnt[4];
    __shared__ float s_ent[CAP];
    __shared__ unsigned char s_keep[CAP];

    int cnt = 0;
    for (int n0 = rlo; n0 < rhi; n0 += 32) {
        int n = n0 + lane;
        bool mem = (n < rhi) && (g_yhat[n] == c);
        cnt += __popc(__ballot_sync(0xffffffffu, mem));
    }
    if (lane == 0) wcnt[wid] = cnt;
    __syncthreads();

    int off = 0;
#pragma unroll
    for (int w = 0; w < 4; w++) if (w < wid) off += wcnt[w];
    int total = wcnt[0] + wcnt[1] + wcnt[2] + wcnt[3];

    int pos = off;
    for (int n0 = rlo; n0 < rhi; n0 += 32) {
        int n = n0 + lane;
        bool mem = (n < rhi) && (g_yhat[n] == c);
        unsigned ball = __ballot_sync(0xffffffffu, mem);
        if (mem) {
            int p = pos + __popc(ball & ((1u << lane) - 1u));
            if (p < CAP) g_list[base + p] = n;
        }
        pos += __popc(ball);
    }
    __syncthreads();

    if (total > CAP) total = CAP;
    const int K = pK[0];

    if (total > K) {
        if (wid == 0) {
            for (int i = lane; i < total; i += 32) s_ent[i] = g_ent[g_list[base + i]];
            __syncwarp();
            for (int i = lane; i < total; i += 32) {
                float ei = s_ent[i];
                int ni = g_list[base + i];
                int rank = 0;
                for (int j = 0; j < total; j++) {
                    float ej = s_ent[j];
                    rank += (ej < ei) || (ej == ei && g_list[base + j] < ni);
                }
                s_keep[i] = (rank < K) ? 1 : 0;
            }
            __syncwarp();
            if (lane == 0) {
                int w = 0;
                for (int i = 0; i < total; i++)
                    if (s_keep[i]) g_list[base + (w++)] = g_list[base + i];
                g_mcnt[c] = w;
            }
        }
    } else if (tid == 0) {
        g_mcnt[c] = total;
    }
}

// ---------------- class prototypes -> normalized bf16 hi/lo weights (padded) ----------------
__global__ __launch_bounds__(256)
void class_weights_kernel(const float* __restrict__ W, const float* __restrict__ z)
{
    const int c = blockIdx.x;
    const int tid = threadIdx.x;

    if (c >= CCLS) {    // zero-fill padding rows
        uint4 zz = make_uint4(0u, 0u, 0u, 0u);
        *reinterpret_cast<uint4*>(g_Wnhi + (size_t)c * DDIM + tid * 8) = zz;
        *reinterpret_cast<uint4*>(g_Wnlo + (size_t)c * DDIM + tid * 8) = zz;
        return;
    }

    float acc[8];
#pragma unroll
    for (int j = 0; j < 8; j++) acc[j] = 0.f;

    const int m = g_mcnt[c];
    const int base = c * CAP;
    for (int i = 0; i < m; i++) {
        const int n = g_list[base + i];
        const float v = g_invn[n];
        const float* row = (n < CCLS) ? (W + (size_t)n * DDIM) : (z + (size_t)(n - CCLS) * DDIM);
        const float4* rp = reinterpret_cast<const float4*>(row + tid * 8);
        float4 a = rp[0], b = rp[1];
        acc[0] += v * a.x; acc[1] += v * a.y; acc[2] += v * a.z; acc[3] += v * a.w;
        acc[4] += v * b.x; acc[5] += v * b.y; acc[6] += v * b.z; acc[7] += v * b.w;
    }

    float ssq = 0.f;
#pragma unroll
    for (int j = 0; j < 8; j++) ssq += acc[j] * acc[j];
    __shared__ float sh[256];
    sh[tid] = ssq;
    __syncthreads();
    for (int s = 128; s > 0; s >>= 1) {
        if (tid < s) sh[tid] += sh[tid + s];
        __syncthreads();
    }
    __shared__ float s_scale;
    if (tid == 0) s_scale = 1.f / fmaxf(sqrtf(sh[0]), 1e-12f);
    __syncthreads();
    const float sc = s_scale;

    __nv_bfloat16 h[8], l[8];
#pragma unroll
    for (int j = 0; j < 8; j++) {
        float x = acc[j] * sc;
        h[j] = __float2bfloat16_rn(x);
        l[j] = __float2bfloat16_rn(x - __bfloat162float(h[j]));
    }
    *reinterpret_cast<uint4*>(g_Wnhi + (size_t)c * DDIM + tid * 8) = *reinterpret_cast<uint4*>(h);
    *reinterpret_cast<uint4*>(g_Wnlo + (size_t)c * DDIM + tid * 8) = *reinterpret_cast<uint4*>(l);
}

// ---------------- launch ----------------
extern "C" void kernel_launch(void* const* d_in, const int* in_sizes, int n_in,
                              void* d_out, int out_size)
{
    const float* z  = (const float*)d_in[0];   // [4096, 2048]
    const float* W  = (const float*)d_in[1];   // [1000, 2048]
    const int*   pK = (const int*)d_in[2];     // filter_K
    float* out = (float*)d_out;                // [4096, 1000]

    static bool attr_done = false;
    if (!attr_done) {
        cudaFuncSetAttribute(mma_gemm_kernel, cudaFuncAttributeMaxDynamicSharedMemorySize, SMEM_TOTAL);
        attr_done = true;
    }

    void* pP = nullptr;    cudaGetSymbolAddress(&pP, g_P);
    void* pP2 = nullptr;   cudaGetSymbolAddress(&pP2, g_P2);
    void* pShi = nullptr;  cudaGetSymbolAddress(&pShi, g_Shi);
    void* pSlo = nullptr;  cudaGetSymbolAddress(&pSlo, g_Slo);
    void* pWnhi = nullptr; cudaGetSymbolAddress(&pWnhi, g_Wnhi);
    void* pWnlo = nullptr; cudaGetSymbolAddress(&pWnlo, g_Wnlo);

    const __nv_bfloat16* Shi = (const __nv_bfloat16*)pShi;
    const __nv_bfloat16* Slo = (const __nv_bfloat16*)pSlo;

    // 1) fp32 -> bf16 hi/lo split of [W; z] (padded) + row inverse norms
    cvt_kernel<<<NPAD, 256>>>(W, z);

    // 2) P = [W; z] @ W^T  (bf16x3 HMMA, split-K=2), [5096, 1000]
    {
        dim3 grid((CCLS + BN - 1) / BN, NPAD / BM, 2);   // 16 x 40 x 2 = 1280
        mma_gemm_kernel<<<grid, 256, SMEM_TOTAL>>>(Shi, Slo, Shi, Slo,
                                                   (float*)pP, (float*)pP2,
                                                   NSUP, (DDIM / BK) / 2);
    }
    // 3) entropy + argmax (sums the two K-partials)
    ent_argmax_kernel<<<NSUP, 256>>>();
    // 4) per-class lists (+ exact top-K)
    build_lists_kernel<<<CCLS, 128>>>(pK);
    // 5) normalized class prototypes -> bf16 hi/lo (BNPAD rows, padding zeroed)
    class_weights_kernel<<<BNPAD, 256>>>(W, z);
    // 6) out = z @ Wn^T  (bf16x3 HMMA, no split), [4096, 1000]
    {
        dim3 grid((CCLS + BN - 1) / BN, BATCH / BM, 1);  // 16 x 32 = 512
        mma_gemm_kernel<<<grid, 256, SMEM_TOTAL>>>(Shi + (size_t)CCLS * DDIM,
                                                   Slo + (size_t)CCLS * DDIM,
                                                   (const __nv_bfloat16*)pWnhi,
                                                   (const __nv_bfloat16*)pWnlo,
                                                   out, out,
                                                   BATCH, DDIM / BK);
    }
}

// round 10
// speedup vs baseline: 5.3268x; 1.8440x over previous
#include <cuda_runtime.h>
#include <cuda_fp16.h>
#include <math.h>
#include <stdint.h>

// ---------------- problem shapes ----------------
#define DDIM  2048
#define CCLS  1000
#define BATCH 4096
#define NSUP  (CCLS + BATCH)   // 5096
#define NPAD  5120             // supports padded to multiple of 128
#define BNPAD 1024             // Wn rows padded
#define CAP   1024

// ---------------- GEMM tiling (single-term fp16) ----------------
#define BM 128
#define BN 64
#define BK 64                  // 64 fp16 = 128B per smem row
#define A_STAGE 16384          // 128 rows x 128B
#define B_STAGE 8192           // 64 rows x 128B
#define STAGE_BYTES (A_STAGE + B_STAGE)   // 24576
#define NSTAGE 4
#define SMEM_TOTAL (NSTAGE * STAGE_BYTES) // 98304

// ---------------- scratch ----------------
__device__ __align__(256) float g_P[(size_t)NSUP * CCLS];    // split-K partial 0
__device__ __align__(256) float g_P2[(size_t)NSUP * CCLS];   // split-K partial 1
__device__ float g_ent[NSUP];
__device__ int   g_yhat[NSUP];
__device__ float g_invn[NSUP];
__device__ int   g_list[CCLS * CAP];
__device__ int   g_mcnt[CCLS];
__device__ __align__(256) __half g_Sh[(size_t)NPAD * DDIM];    // fp16 supports [W; z]
__device__ __align__(256) __half g_Wnh[(size_t)BNPAD * DDIM];  // fp16 normalized prototypes

// ---------------- PTX helpers (baseline compute_103-safe) ----------------
__device__ __forceinline__ uint32_t smem_u32(const void* p) {
    uint32_t a;
    asm("{ .reg .u64 t; cvta.to.shared.u64 t, %1; cvt.u32.u64 %0, t; }" : "=r"(a) : "l"(p));
    return a;
}
#define CP_ASYNC16(dst, src) \
    asm volatile("cp.async.cg.shared.global [%0], [%1], 16;" :: "r"(dst), "l"(src) : "memory")
#define CP_COMMIT() asm volatile("cp.async.commit_group;" ::: "memory")
#define CP_WAIT(N)  asm volatile("cp.async.wait_group %0;" :: "n"(N) : "memory")

__device__ __forceinline__ void ldsm4(uint32_t* r, uint32_t addr) {
    asm volatile("ldmatrix.sync.aligned.m8n8.x4.shared.b16 {%0,%1,%2,%3}, [%4];"
                 : "=r"(r[0]), "=r"(r[1]), "=r"(r[2]), "=r"(r[3]) : "r"(addr));
}
__device__ __forceinline__ void mma16816h(float* c, const uint32_t* a, uint32_t b0, uint32_t b1) {
    asm volatile("mma.sync.aligned.m16n8k16.row.col.f32.f16.f16.f32 "
                 "{%0,%1,%2,%3}, {%4,%5,%6,%7}, {%8,%9}, {%0,%1,%2,%3};"
                 : "+f"(c[0]), "+f"(c[1]), "+f"(c[2]), "+f"(c[3])
                 : "r"(a[0]), "r"(a[1]), "r"(a[2]), "r"(a[3]), "r"(b0), "r"(b1));
}

// ---------------- conversion (fp32 -> fp16) + row inverse norms ----------------
__global__ __launch_bounds__(256)
void cvt_kernel(const float* __restrict__ W, const float* __restrict__ z)
{
    const int r = blockIdx.x;
    const int tid = threadIdx.x;
    __half* dst = g_Sh + (size_t)r * DDIM + tid * 8;

    if (r >= NSUP) {
        *reinterpret_cast<uint4*>(dst) = make_uint4(0u, 0u, 0u, 0u);
        return;
    }
    const float* src = (r < CCLS) ? (W + (size_t)r * DDIM) : (z + (size_t)(r - CCLS) * DDIM);
    const float4* sp = reinterpret_cast<const float4*>(src + tid * 8);
    float4 a = sp[0], b = sp[1];
    float x[8] = {a.x, a.y, a.z, a.w, b.x, b.y, b.z, b.w};

    __half h[8];
    float ssq = 0.f;
#pragma unroll
    for (int j = 0; j < 8; j++) {
        ssq += x[j] * x[j];
        h[j] = __float2half_rn(x[j]);
    }
    *reinterpret_cast<uint4*>(dst) = *reinterpret_cast<uint4*>(h);

    __shared__ float sh[256];
    sh[tid] = ssq;
    __syncthreads();
    for (int s = 128; s > 0; s >>= 1) {
        if (tid < s) sh[tid] += sh[tid + s];
        __syncthreads();
    }
    if (tid == 0) g_invn[r] = 1.f / fmaxf(sqrtf(sh[0]), 1e-12f);
}

// ---------------- fp16 GEMM via mma.sync: C[m][n] = sum_k A[m][k]*B[n][k] ----------------
// smem per stage: A (128 x 128B) then B (64 x 128B); row r holds 64 fp16 (one BK chunk),
// 8 quads of 16B; phys quad = q ^ (r & 7).
__device__ __forceinline__ void load_stage(uint32_t sbase, int stage, int k0,
    const __half* __restrict__ A, const __half* __restrict__ B,
    int m0, int n0, int tid)
{
    const uint32_t sb = sbase + stage * STAGE_BYTES;
    const int kq = tid & 7;   // quad within row
#pragma unroll
    for (int p = 0; p < 6; ++p) {
        const int v = p * 256 + tid;                 // 0..1535
        const bool isB = (v >= 1024);
        const int row = (isB ? (v - 1024) : v) >> 3;
        const int grow = (isB ? n0 : m0) + row;
        const __half* g = (isB ? B : A) + (size_t)grow * DDIM + k0 + kq * 8;
        const uint32_t dst = sb + (isB ? A_STAGE : 0)
                           + row * 128 + ((kq ^ (row & 7)) * 16);
        CP_ASYNC16(dst, g);
    }
}

// kchunks BK-chunks per CTA; k origin = blockIdx.z * kchunks * BK; C = (z ? C1 : C0).
__global__ __launch_bounds__(256, 2)
void mma_gemm_kernel(const __half* __restrict__ A, const __half* __restrict__ B,
                     float* __restrict__ C0, float* __restrict__ C1,
                     int M, int kchunks)
{
    extern __shared__ __align__(128) char sm[];
    const int tid = threadIdx.x;
    const int wid = tid >> 5;
    const int lane = tid & 31;
    const int wm = wid & 3;        // 4 m-warps x 32 rows
    const int wn = wid >> 2;       // 2 n-warps x 32 cols
    const int m0 = blockIdx.y * BM;
    const int n0 = blockIdx.x * BN;
    const int kb = blockIdx.z * kchunks * BK;
    float* __restrict__ C = blockIdx.z ? C1 : C0;
    const uint32_t sb = smem_u32(sm);

    const int li = lane & 7;
    const int lg = lane >> 3;
    const int rofs = (lg & 1) * 8 + li;   // row within 16-row tile
    const int qofs = lg >> 1;             // k8 selector within k16

    float acc[2][4][4];
#pragma unroll
    for (int a = 0; a < 2; a++)
#pragma unroll
        for (int b = 0; b < 4; b++)
#pragma unroll
            for (int cc = 0; cc < 4; cc++) acc[a][b][cc] = 0.f;

    load_stage(sb, 0, kb, A, B, m0, n0, tid);
    CP_COMMIT();
    load_stage(sb, 1, kb + BK, A, B, m0, n0, tid);
    CP_COMMIT();
    load_stage(sb, 2, kb + 2 * BK, A, B, m0, n0, tid);
    CP_COMMIT();

#pragma unroll 1
    for (int c = 0; c < kchunks; ++c) {
        const int s = c & 3;
        const int rem = kchunks - 1 - c;
        if (rem >= 2)      { CP_WAIT(2); }
        else if (rem == 1) { CP_WAIT(1); }
        else               { CP_WAIT(0); }
        __syncthreads();
        if (c + 3 < kchunks) {
            load_stage(sb, (c + 3) & 3, kb + (c + 3) * BK, A, B, m0, n0, tid);
            CP_COMMIT();
        }

        const uint32_t Ab = sb + s * STAGE_BYTES;
        const uint32_t Bb = Ab + A_STAGE;
#pragma unroll
        for (int ks = 0; ks < 4; ++ks) {           // 4 k16 steps per BK=64 chunk
            const int qh = ks * 2 + qofs;          // quad 0..7
            uint32_t af[2][4];
#pragma unroll
            for (int mt = 0; mt < 2; ++mt) {
                const int r = wm * 32 + mt * 16 + rofs;
                ldsm4(af[mt], Ab + r * 128 + ((qh ^ (r & 7)) * 16));
            }
#pragma unroll
            for (int ng = 0; ng < 2; ++ng) {
                const int rn = wn * 32 + ng * 16 + rofs;
                uint32_t bf[4];
                ldsm4(bf, Bb + rn * 128 + ((qh ^ (rn & 7)) * 16));
#pragma unroll
                for (int mt = 0; mt < 2; ++mt) {
#pragma unroll
                    for (int h = 0; h < 2; ++h)
                        mma16816h(acc[mt][ng * 2 + h], af[mt], bf[h], bf[h + 2]);
                }
            }
        }
    }

    // epilogue
    const int mrow = m0 + wm * 32 + (lane >> 2);
    const int ncol = n0 + wn * 32 + (lane & 3) * 2;
#pragma unroll
    for (int mt = 0; mt < 2; ++mt) {
#pragma unroll
        for (int nt = 0; nt < 4; ++nt) {
            const int m = mrow + mt * 16;
            const int n = ncol + nt * 8;
            float* cc = acc[mt][nt];
            if (n < CCLS) {
                if (m < M)
                    *reinterpret_cast<float2*>(C + (size_t)m * CCLS + n) = make_float2(cc[0], cc[1]);
                if (m + 8 < M)
                    *reinterpret_cast<float2*>(C + (size_t)(m + 8) * CCLS + n) = make_float2(cc[2], cc[3]);
            }
        }
    }
}

// ---------------- entropy + exact-repaired argmax ----------------
// Logits are fp16-approximate (abs err ~5e-4). Entropy from approx logits is fine
// (only used for intra-class ordering, inactive when counts < K). Argmax is repaired:
// take approximate top-4 columns, recompute those 4 logits exactly in fp32, pick max
// (ties -> smaller index).
__global__ __launch_bounds__(256)
void ent_argmax_fix_kernel(const float* __restrict__ W, const float* __restrict__ z)
{
    const int r = blockIdx.x;
    const float* row0 = g_P  + (size_t)r * CCLS;
    const float* row1 = g_P2 + (size_t)r * CCLS;
    const int tid = threadIdx.x;
    const int wid = tid >> 5;
    const int lane = tid & 31;

    float v[4];
#pragma unroll
    for (int t = 0; t < 4; t++) {
        const int j = tid + t * 256;
        v[t] = (j < CCLS) ? (row0[j] + row1[j]) : -3.402823466e38f;
    }

    __shared__ float wv[8];
    __shared__ int   wi[8];
    __shared__ float ws[8], wd[8];
    __shared__ int   s_cand[4];
    __shared__ float s_exact[4];
    __shared__ float s_m;

    // approx max (value only) for entropy stability
    {
        float lm = fmaxf(fmaxf(v[0], v[1]), fmaxf(v[2], v[3]));
#pragma unroll
        for (int o = 16; o > 0; o >>= 1) lm = fmaxf(lm, __shfl_down_sync(0xffffffffu, lm, o));
        if (lane == 0) wv[wid] = lm;
        __syncthreads();
        if (tid == 0) {
            float m = wv[0];
#pragma unroll
            for (int w = 1; w < 8; w++) m = fmaxf(m, wv[w]);
            s_m = m;
        }
        __syncthreads();
    }
    const float m = s_m;

    // entropy sums
    {
        float s = 0.f, d = 0.f;
#pragma unroll
        for (int t = 0; t < 4; t++) {
            const int j = tid + t * 256;
            if (j < CCLS) {
                float e = __expf(v[t] - m);
                s += e; d += e * v[t];
            }
        }
#pragma unroll
        for (int o = 16; o > 0; o >>= 1) {
            s += __shfl_down_sync(0xffffffffu, s, o);
            d += __shfl_down_sync(0xffffffffu, d, o);
        }
        if (lane == 0) { ws[wid] = s; wd[wid] = d; }
    }

    // approximate top-4 (distinct indices, ties -> smaller index)
    bool taken[4] = {false, false, false, false};
#pragma unroll 1
    for (int t = 0; t < 4; ++t) {
        float bv = -3.402823466e38f;
        int   bi = 0x7fffffff;
#pragma unroll
        for (int q = 0; q < 4; q++) {
            if (!taken[q]) {
                const int jq = tid + q * 256;
                if (v[q] > bv || (v[q] == bv && jq < bi)) { bv = v[q]; bi = jq; }
            }
        }
#pragma unroll
        for (int o = 16; o > 0; o >>= 1) {
            float v2 = __shfl_down_sync(0xffffffffu, bv, o);
            int   i2 = __shfl_down_sync(0xffffffffu, bi, o);
            if (v2 > bv || (v2 == bv && i2 < bi)) { bv = v2; bi = i2; }
        }
        if (lane == 0) { wv[wid] = bv; wi[wid] = bi; }
        __syncthreads();
        if (tid == 0) {
            float bm = wv[0]; int bj = wi[0];
#pragma unroll
            for (int w = 1; w < 8; w++) {
                if (wv[w] > bm || (wv[w] == bm && wi[w] < bj)) { bm = wv[w]; bj = wi[w]; }
            }
            s_cand[t] = bj;
        }
        __syncthreads();
        const int widx = s_cand[t];
        if ((widx & 255) == tid) taken[widx >> 8] = true;
    }

    // exact fp32 recompute of the 4 candidate logits (warps 0-3)
    if (wid < 4) {
        const int cj = s_cand[wid];
        const float* arow = (r < CCLS) ? (W + (size_t)r * DDIM) : (z + (size_t)(r - CCLS) * DDIM);
        const float* brow = W + (size_t)cj * DDIM;
        float acc = 0.f;
        for (int dd = lane * 4; dd < DDIM; dd += 128) {
            float4 a4 = *reinterpret_cast<const float4*>(arow + dd);
            float4 b4 = *reinterpret_cast<const float4*>(brow + dd);
            acc = fmaf(a4.x, b4.x, acc);
            acc = fmaf(a4.y, b4.y, acc);
            acc = fmaf(a4.z, b4.z, acc);
            acc = fmaf(a4.w, b4.w, acc);
        }
#pragma unroll
        for (int o = 16; o > 0; o >>= 1) acc += __shfl_down_sync(0xffffffffu, acc, o);
        if (lane == 0) s_exact[wid] = acc;
    }
    __syncthreads();

    if (tid == 0) {
        float bm = s_exact[0]; int bj = s_cand[0];
#pragma unroll
        for (int t = 1; t < 4; t++) {
            if (s_exact[t] > bm || (s_exact[t] == bm && s_cand[t] < bj)) { bm = s_exact[t]; bj = s_cand[t]; }
        }
        g_yhat[r] = bj;
        float S = 0.f, D = 0.f;
#pragma unroll
        for (int w = 0; w < 8; w++) { S += ws[w]; D += wd[w]; }
        g_ent[r] = m + logf(S) - D / S;
    }
}

// ---------------- per-class member lists ----------------
__global__ void build_lists_kernel(const int* __restrict__ pK)
{
    const int c = blockIdx.x;
    const int tid = threadIdx.x;        // 128 threads
    const int wid = tid >> 5;
    const int lane = tid & 31;
    const int base = c * CAP;
    const int per = (NSUP + 3) / 4;
    const int rlo = wid * per;
    const int rhi = min(rlo + per, NSUP);

    __shared__ int wcnt[4];
    __shared__ float s_ent[CAP];
    __shared__ unsigned char s_keep[CAP];

    int cnt = 0;
    for (int n0 = rlo; n0 < rhi; n0 += 32) {
        int n = n0 + lane;
        bool mem = (n < rhi) && (g_yhat[n] == c);
        cnt += __popc(__ballot_sync(0xffffffffu, mem));
    }
    if (lane == 0) wcnt[wid] = cnt;
    __syncthreads();

    int off = 0;
#pragma unroll
    for (int w = 0; w < 4; w++) if (w < wid) off += wcnt[w];
    int total = wcnt[0] + wcnt[1] + wcnt[2] + wcnt[3];

    int pos = off;
    for (int n0 = rlo; n0 < rhi; n0 += 32) {
        int n = n0 + lane;
        bool mem = (n < rhi) && (g_yhat[n] == c);
        unsigned ball = __ballot_sync(0xffffffffu, mem);
        if (mem) {
            int p = pos + __popc(ball & ((1u << lane) - 1u));
            if (p < CAP) g_list[base + p] = n;
        }
        pos += __popc(ball);
    }
    __syncthreads();

    if (total > CAP) total = CAP;
    const int K = pK[0];

    if (total > K) {
        if (wid == 0) {
            for (int i = lane; i < total; i += 32) s_ent[i] = g_ent[g_list[base + i]];
            __syncwarp();
            for (int i = lane; i < total; i += 32) {
                float ei = s_ent[i];
                int ni = g_list[base + i];
                int rank = 0;
                for (int j = 0; j < total; j++) {
                    float ej = s_ent[j];
                    rank += (ej < ei) || (ej == ei && g_list[base + j] < ni);
                }
                s_keep[i] = (rank < K) ? 1 : 0;
            }
            __syncwarp();
            if (lane == 0) {
                int w = 0;
                for (int i = 0; i < total; i++)
                    if (s_keep[i]) g_list[base + (w++)] = g_list[base + i];
                g_mcnt[c] = w;
            }
        }
    } else if (tid == 0) {
        g_mcnt[c] = total;
    }
}

// ---------------- class prototypes -> normalized fp16 weights (padded) ----------------
__global__ __launch_bounds__(256)
void class_weights_kernel(const float* __restrict__ W, const float* __restrict__ z)
{
    const int c = blockIdx.x;
    const int tid = threadIdx.x;

    if (c >= CCLS) {
        *reinterpret_cast<uint4*>(g_Wnh + (size_t)c * DDIM + tid * 8) = make_uint4(0u, 0u, 0u, 0u);
        return;
    }

    float acc[8];
#pragma unroll
    for (int j = 0; j < 8; j++) acc[j] = 0.f;

    const int m = g_mcnt[c];
    const int base = c * CAP;
    for (int i = 0; i < m; i++) {
        const int n = g_list[base + i];
        const float v = g_invn[n];
        const float* row = (n < CCLS) ? (W + (size_t)n * DDIM) : (z + (size_t)(n - CCLS) * DDIM);
        const float4* rp = reinterpret_cast<const float4*>(row + tid * 8);
        float4 a = rp[0], b = rp[1];
        acc[0] += v * a.x; acc[1] += v * a.y; acc[2] += v * a.z; acc[3] += v * a.w;
        acc[4] += v * b.x; acc[5] += v * b.y; acc[6] += v * b.z; acc[7] += v * b.w;
    }

    float ssq = 0.f;
#pragma unroll
    for (int j = 0; j < 8; j++) ssq += acc[j] * acc[j];
    __shared__ float sh[256];
    sh[tid] = ssq;
    __syncthreads();
    for (int s = 128; s > 0; s >>= 1) {
        if (tid < s) sh[tid] += sh[tid + s];
        __syncthreads();
    }
    __shared__ float s_scale;
    if (tid == 0) s_scale = 1.f / fmaxf(sqrtf(sh[0]), 1e-12f);
    __syncthreads();
    const float sc = s_scale;

    __half h[8];
#pragma unroll
    for (int j = 0; j < 8; j++) h[j] = __float2half_rn(acc[j] * sc);
    *reinterpret_cast<uint4*>(g_Wnh + (size_t)c * DDIM + tid * 8) = *reinterpret_cast<uint4*>(h);
}

// ---------------- launch ----------------
extern "C" void kernel_launch(void* const* d_in, const int* in_sizes, int n_in,
                              void* d_out, int out_size)
{
    const float* z  = (const float*)d_in[0];   // [4096, 2048]
    const float* W  = (const float*)d_in[1];   // [1000, 2048]
    const int*   pK = (const int*)d_in[2];     // filter_K
    float* out = (float*)d_out;                // [4096, 1000]

    static bool attr_done = false;
    if (!attr_done) {
        cudaFuncSetAttribute(mma_gemm_kernel, cudaFuncAttributeMaxDynamicSharedMemorySize, SMEM_TOTAL);
        attr_done = true;
    }

    void* pP = nullptr;   cudaGetSymbolAddress(&pP, g_P);
    void* pP2 = nullptr;  cudaGetSymbolAddress(&pP2, g_P2);
    void* pSh = nullptr;  cudaGetSymbolAddress(&pSh, g_Sh);
    void* pWnh = nullptr; cudaGetSymbolAddress(&pWnh, g_Wnh);

    const __half* Sh = (const __half*)pSh;

    // 1) fp32 -> fp16 supports [W; z] (padded) + row inverse norms
    cvt_kernel<<<NPAD, 256>>>(W, z);

    // 2) P ~= [W; z] @ W^T  (single fp16 HMMA, split-K=2), [5096, 1000]
    {
        dim3 grid((CCLS + BN - 1) / BN, NPAD / BM, 2);   // 16 x 40 x 2
        mma_gemm_kernel<<<grid, 256, SMEM_TOTAL>>>(Sh, Sh, (float*)pP, (float*)pP2,
                                                   NSUP, (DDIM / BK) / 2);
    }
    // 3) entropy (approx) + exact-repaired argmax
    ent_argmax_fix_kernel<<<NSUP, 256>>>(W, z);
    // 4) per-class lists (+ exact top-K)
    build_lists_kernel<<<CCLS, 128>>>(pK);
    // 5) normalized class prototypes -> fp16 (padded rows zeroed)
    class_weights_kernel<<<BNPAD, 256>>>(W, z);
    // 6) out = z @ Wn^T  (single fp16 HMMA), [4096, 1000]
    {
        dim3 grid((CCLS + BN - 1) / BN, BATCH / BM, 1);  // 16 x 32
        mma_gemm_kernel<<<grid, 256, SMEM_TOTAL>>>(Sh + (size_t)CCLS * DDIM,
                                                   (const __half*)pWnh,
                                                   out, out,
                                                   BATCH, DDIM / BK);
    }
}

// round 14
// speedup vs baseline: 5.5297x; 1.0381x over previous
#include <cuda_runtime.h>
#include <cuda_fp16.h>
#include <math.h>
#include <stdint.h>

// ---------------- problem shapes ----------------
#define DDIM  2048
#define CCLS  1000
#define BATCH 4096
#define NSUP  (CCLS + BATCH)   // 5096
#define NPAD  5120             // supports padded to multiple of 128
#define BNPAD 1024             // Wn rows padded
#define CAP   1024

// ---------------- GEMM tiling (single-term fp16) ----------------
#define BM 128
#define BN 64
#define BK 64                  // 64 fp16 = 128B per smem row
#define A_STAGE 16384          // 128 rows x 128B
#define B_STAGE 8192           // 64 rows x 128B
#define STAGE_BYTES (A_STAGE + B_STAGE)   // 24576
#define NSTAGE 4
#define SMEM_TOTAL (NSTAGE * STAGE_BYTES) // 98304

// ---------------- scratch ----------------
__device__ __align__(256) float g_P[(size_t)NSUP * CCLS];    // split-K partial 0
__device__ __align__(256) float g_P2[(size_t)NSUP * CCLS];   // split-K partial 1
__device__ float g_ent[NSUP];
__device__ int   g_yhat[NSUP];
__device__ float g_invn[NSUP];
__device__ int   g_list[CCLS * CAP];
__device__ int   g_mcnt[CCLS];
__device__ __align__(256) __half g_Sh[(size_t)NPAD * DDIM];    // fp16 supports [W; z]
__device__ __align__(256) __half g_Wnh[(size_t)BNPAD * DDIM];  // fp16 normalized prototypes

// ---------------- PTX helpers (baseline compute_103-safe) ----------------
__device__ __forceinline__ uint32_t smem_u32(const void* p) {
    uint32_t a;
    asm("{ .reg .u64 t; cvta.to.shared.u64 t, %1; cvt.u32.u64 %0, t; }" : "=r"(a) : "l"(p));
    return a;
}
#define CP_ASYNC16(dst, src) \
    asm volatile("cp.async.cg.shared.global [%0], [%1], 16;" :: "r"(dst), "l"(src) : "memory")
#define CP_COMMIT() asm volatile("cp.async.commit_group;" ::: "memory")
#define CP_WAIT(N)  asm volatile("cp.async.wait_group %0;" :: "n"(N) : "memory")

__device__ __forceinline__ void ldsm4(uint32_t* r, uint32_t addr) {
    asm volatile("ldmatrix.sync.aligned.m8n8.x4.shared.b16 {%0,%1,%2,%3}, [%4];"
                 : "=r"(r[0]), "=r"(r[1]), "=r"(r[2]), "=r"(r[3]) : "r"(addr));
}
__device__ __forceinline__ void mma16816h(float* c, const uint32_t* a, uint32_t b0, uint32_t b1) {
    asm volatile("mma.sync.aligned.m16n8k16.row.col.f32.f16.f16.f32 "
                 "{%0,%1,%2,%3}, {%4,%5,%6,%7}, {%8,%9}, {%0,%1,%2,%3};"
                 : "+f"(c[0]), "+f"(c[1]), "+f"(c[2]), "+f"(c[3])
                 : "r"(a[0]), "r"(a[1]), "r"(a[2]), "r"(a[3]), "r"(b0), "r"(b1));
}

// ---------------- conversion (fp32 -> fp16) + row inverse norms ----------------
__global__ __launch_bounds__(256)
void cvt_kernel(const float* __restrict__ W, const float* __restrict__ z)
{
    const int r = blockIdx.x;
    const int tid = threadIdx.x;
    __half* dst = g_Sh + (size_t)r * DDIM + tid * 8;

    if (r >= NSUP) {
        *reinterpret_cast<uint4*>(dst) = make_uint4(0u, 0u, 0u, 0u);
        return;
    }
    const float* src = (r < CCLS) ? (W + (size_t)r * DDIM) : (z + (size_t)(r - CCLS) * DDIM);
    const float4* sp = reinterpret_cast<const float4*>(src + tid * 8);
    float4 a = sp[0], b = sp[1];
    float x[8] = {a.x, a.y, a.z, a.w, b.x, b.y, b.z, b.w};

    __half h[8];
    float ssq = 0.f;
#pragma unroll
    for (int j = 0; j < 8; j++) {
        ssq += x[j] * x[j];
        h[j] = __float2half_rn(x[j]);
    }
    *reinterpret_cast<uint4*>(dst) = *reinterpret_cast<uint4*>(h);

    __shared__ float sh[256];
    sh[tid] = ssq;
    __syncthreads();
    for (int s = 128; s > 0; s >>= 1) {
        if (tid < s) sh[tid] += sh[tid + s];
        __syncthreads();
    }
    if (tid == 0) g_invn[r] = 1.f / fmaxf(sqrtf(sh[0]), 1e-12f);
}

// ---------------- fp16 GEMM via mma.sync: C[m][n] = sum_k A[m][k]*B[n][k] ----------------
__device__ __forceinline__ void load_stage(uint32_t sbase, int stage, int k0,
    const __half* __restrict__ A, const __half* __restrict__ B,
    int m0, int n0, int tid)
{
    const uint32_t sb = sbase + stage * STAGE_BYTES;
    const int kq = tid & 7;   // quad within row
#pragma unroll
    for (int p = 0; p < 6; ++p) {
        const int v = p * 256 + tid;                 // 0..1535
        const bool isB = (v >= 1024);
        const int row = (isB ? (v - 1024) : v) >> 3;
        const int grow = (isB ? n0 : m0) + row;
        const __half* g = (isB ? B : A) + (size_t)grow * DDIM + k0 + kq * 8;
        const uint32_t dst = sb + (isB ? A_STAGE : 0)
                           + row * 128 + ((kq ^ (row & 7)) * 16);
        CP_ASYNC16(dst, g);
    }
}

__global__ __launch_bounds__(256, 2)
void mma_gemm_kernel(const __half* __restrict__ A, const __half* __restrict__ B,
                     float* __restrict__ C0, float* __restrict__ C1,
                     int M, int kchunks)
{
    extern __shared__ __align__(128) char sm[];
    const int tid = threadIdx.x;
    const int wid = tid >> 5;
    const int lane = tid & 31;
    const int wm = wid & 3;        // 4 m-warps x 32 rows
    const int wn = wid >> 2;       // 2 n-warps x 32 cols
    const int m0 = blockIdx.y * BM;
    const int n0 = blockIdx.x * BN;
    const int kb = blockIdx.z * kchunks * BK;
    float* __restrict__ C = blockIdx.z ? C1 : C0;
    const uint32_t sb = smem_u32(sm);

    const int li = lane & 7;
    const int lg = lane >> 3;
    const int rofs = (lg & 1) * 8 + li;   // row within 16-row tile
    const int qofs = lg >> 1;             // k8 selector within k16

    float acc[2][4][4];
#pragma unroll
    for (int a = 0; a < 2; a++)
#pragma unroll
        for (int b = 0; b < 4; b++)
#pragma unroll
            for (int cc = 0; cc < 4; cc++) acc[a][b][cc] = 0.f;

    load_stage(sb, 0, kb, A, B, m0, n0, tid);
    CP_COMMIT();
    load_stage(sb, 1, kb + BK, A, B, m0, n0, tid);
    CP_COMMIT();
    load_stage(sb, 2, kb + 2 * BK, A, B, m0, n0, tid);
    CP_COMMIT();

#pragma unroll 1
    for (int c = 0; c < kchunks; ++c) {
        const int s = c & 3;
        const int rem = kchunks - 1 - c;
        if (rem >= 2)      { CP_WAIT(2); }
        else if (rem == 1) { CP_WAIT(1); }
        else               { CP_WAIT(0); }
        __syncthreads();
        if (c + 3 < kchunks) {
            load_stage(sb, (c + 3) & 3, kb + (c + 3) * BK, A, B, m0, n0, tid);
            CP_COMMIT();
        }

        const uint32_t Ab = sb + s * STAGE_BYTES;
        const uint32_t Bb = Ab + A_STAGE;
#pragma unroll
        for (int ks = 0; ks < 4; ++ks) {           // 4 k16 steps per BK=64 chunk
            const int qh = ks * 2 + qofs;
            uint32_t af[2][4];
#pragma unroll
            for (int mt = 0; mt < 2; ++mt) {
                const int r = wm * 32 + mt * 16 + rofs;
                ldsm4(af[mt], Ab + r * 128 + ((qh ^ (r & 7)) * 16));
            }
#pragma unroll
            for (int ng = 0; ng < 2; ++ng) {
                const int rn = wn * 32 + ng * 16 + rofs;
                uint32_t bf[4];
                ldsm4(bf, Bb + rn * 128 + ((qh ^ (rn & 7)) * 16));
#pragma unroll
                for (int mt = 0; mt < 2; ++mt) {
#pragma unroll
                    for (int h = 0; h < 2; ++h)
                        mma16816h(acc[mt][ng * 2 + h], af[mt], bf[h], bf[h + 2]);
                }
            }
        }
    }

    const int mrow = m0 + wm * 32 + (lane >> 2);
    const int ncol = n0 + wn * 32 + (lane & 3) * 2;
#pragma unroll
    for (int mt = 0; mt < 2; ++mt) {
#pragma unroll
        for (int nt = 0; nt < 4; ++nt) {
            const int m = mrow + mt * 16;
            const int n = ncol + nt * 8;
            float* cc = acc[mt][nt];
            if (n < CCLS) {
                if (m < M)
                    *reinterpret_cast<float2*>(C + (size_t)m * CCLS + n) = make_float2(cc[0], cc[1]);
                if (m + 8 < M)
                    *reinterpret_cast<float2*>(C + (size_t)(m + 8) * CCLS + n) = make_float2(cc[2], cc[3]);
            }
        }
    }
}

// ---------------- entropy + exact-repaired argmax + fused class scatter ----------------
__global__ __launch_bounds__(256)
void ent_argmax_fix_kernel(const float* __restrict__ W, const float* __restrict__ z)
{
    const int r = blockIdx.x;
    const float* row0 = g_P  + (size_t)r * CCLS;
    const float* row1 = g_P2 + (size_t)r * CCLS;
    const int tid = threadIdx.x;
    const int wid = tid >> 5;
    const int lane = tid & 31;

    float v[4];
#pragma unroll
    for (int t = 0; t < 4; t++) {
        const int j = tid + t * 256;
        v[t] = (j < CCLS) ? (row0[j] + row1[j]) : -3.402823466e38f;
    }

    __shared__ float wv[8];
    __shared__ int   wi[8];
    __shared__ float ws[8], wd[8];
    __shared__ int   s_cand[4];
    __shared__ float s_exact[4];
    __shared__ float s_m;

    // approx max (value only) for entropy stability
    {
        float lm = fmaxf(fmaxf(v[0], v[1]), fmaxf(v[2], v[3]));
#pragma unroll
        for (int o = 16; o > 0; o >>= 1) lm = fmaxf(lm, __shfl_down_sync(0xffffffffu, lm, o));
        if (lane == 0) wv[wid] = lm;
        __syncthreads();
        if (tid == 0) {
            float m = wv[0];
#pragma unroll
            for (int w = 1; w < 8; w++) m = fmaxf(m, wv[w]);
            s_m = m;
        }
        __syncthreads();
    }
    const float m = s_m;

    // entropy sums
    {
        float s = 0.f, d = 0.f;
#pragma unroll
        for (int t = 0; t < 4; t++) {
            const int j = tid + t * 256;
            if (j < CCLS) {
                float e = __expf(v[t] - m);
                s += e; d += e * v[t];
            }
        }
#pragma unroll
        for (int o = 16; o > 0; o >>= 1) {
            s += __shfl_down_sync(0xffffffffu, s, o);
            d += __shfl_down_sync(0xffffffffu, d, o);
        }
        if (lane == 0) { ws[wid] = s; wd[wid] = d; }
    }

    // approximate top-4 (distinct indices, ties -> smaller index)
    bool taken[4] = {false, false, false, false};
#pragma unroll 1
    for (int t = 0; t < 4; ++t) {
        float bv = -3.402823466e38f;
        int   bi = 0x7fffffff;
#pragma unroll
        for (int q = 0; q < 4; q++) {
            if (!taken[q]) {
                const int jq = tid + q * 256;
                if (v[q] > bv || (v[q] == bv && jq < bi)) { bv = v[q]; bi = jq; }
            }
        }
#pragma unroll
        for (int o = 16; o > 0; o >>= 1) {
            float v2 = __shfl_down_sync(0xffffffffu, bv, o);
            int   i2 = __shfl_down_sync(0xffffffffu, bi, o);
            if (v2 > bv || (v2 == bv && i2 < bi)) { bv = v2; bi = i2; }
        }
        if (lane == 0) { wv[wid] = bv; wi[wid] = bi; }
        __syncthreads();
        if (tid == 0) {
            float bm = wv[0]; int bj = wi[0];
#pragma unroll
            for (int w = 1; w < 8; w++) {
                if (wv[w] > bm || (wv[w] == bm && wi[w] < bj)) { bm = wv[w]; bj = wi[w]; }
            }
            s_cand[t] = bj;
        }
        __syncthreads();
        const int widx = s_cand[t];
        if ((widx & 255) == tid) taken[widx >> 8] = true;
    }

    // exact fp32 recompute of the 4 candidate logits (warps 0-3)
    if (wid < 4) {
        const int cj = s_cand[wid];
        const float* arow = (r < CCLS) ? (W + (size_t)r * DDIM) : (z + (size_t)(r - CCLS) * DDIM);
        const float* brow = W + (size_t)cj * DDIM;
        float acc = 0.f;
        for (int dd = lane * 4; dd < DDIM; dd += 128) {
            float4 a4 = *reinterpret_cast<const float4*>(arow + dd);
            float4 b4 = *reinterpret_cast<const float4*>(brow + dd);
            acc = fmaf(a4.x, b4.x, acc);
            acc = fmaf(a4.y, b4.y, acc);
            acc = fmaf(a4.z, b4.z, acc);
            acc = fmaf(a4.w, b4.w, acc);
        }
#pragma unroll
        for (int o = 16; o > 0; o >>= 1) acc += __shfl_down_sync(0xffffffffu, acc, o);
        if (lane == 0) s_exact[wid] = acc;
    }
    __syncthreads();

    if (tid == 0) {
        float bm = s_exact[0]; int bj = s_cand[0];
#pragma unroll
        for (int t = 1; t < 4; t++) {
            if (s_exact[t] > bm || (s_exact[t] == bm && s_cand[t] < bj)) { bm = s_exact[t]; bj = s_cand[t]; }
        }
        g_yhat[r] = bj;
        float S = 0.f, D = 0.f;
#pragma unroll
        for (int w = 0; w < 8; w++) { S += ws[w]; D += wd[w]; }
        g_ent[r] = m + logf(S) - D / S;
        // fused scatter into per-class list (order repaired by sortsel_kernel)
        const int pos = atomicAdd(&g_mcnt[bj], 1);
        if (pos < CAP) g_list[bj * CAP + pos] = r;
    }
}

// ---------------- per-class deterministic sort + exact top-K ----------------
// one warp per class: sort member list by support index (restores determinism after
// atomic scatter), then exact entropy top-K (ties -> smaller index) if count > K.
__global__ __launch_bounds__(32)
void sortsel_kernel(const int* __restrict__ pK)
{
    const int c = blockIdx.x;
    const int lane = threadIdx.x;
    const int base = c * CAP;

    __shared__ int   s_idx[CAP];
    __shared__ int   s_sorted[CAP];
    __shared__ float s_ent[CAP];
    __shared__ unsigned char s_keep[CAP];

    int cnt = g_mcnt[c];
    if (cnt > CAP) cnt = CAP;
    if (cnt == 0) { if (lane == 0) g_mcnt[c] = 0; return; }

    for (int i = lane; i < cnt; i += 32) s_idx[i] = g_list[base + i];
    __syncwarp();

    // rank sort by support index (all distinct)
    for (int i = lane; i < cnt; i += 32) {
        const int vi = s_idx[i];
        int rank = 0;
        for (int j = 0; j < cnt; j++) rank += (s_idx[j] < vi);
        s_sorted[rank] = vi;
    }
    __syncwarp();

    const int K = pK[0];
    if (cnt > K) {
        for (int i = lane; i < cnt; i += 32) s_ent[i] = g_ent[s_sorted[i]];
        __syncwarp();
        for (int i = lane; i < cnt; i += 32) {
            const float ei = s_ent[i];
            const int ni = s_sorted[i];
            int rank = 0;
            for (int j = 0; j < cnt; j++) {
                const float ej = s_ent[j];
                rank += (ej < ei) || (ej == ei && s_sorted[j] < ni);
            }
            s_keep[i] = (rank < K) ? 1 : 0;
        }
        __syncwarp();
        if (lane == 0) {
            int w = 0;
            for (int i = 0; i < cnt; i++)
                if (s_keep[i]) g_list[base + (w++)] = s_sorted[i];
            g_mcnt[c] = w;
        }
    } else {
        for (int i = lane; i < cnt; i += 32) g_list[base + i] = s_sorted[i];
        if (lane == 0) g_mcnt[c] = cnt;
    }
}

// ---------------- class prototypes -> normalized fp16 weights (padded) ----------------
__global__ __launch_bounds__(256)
void class_weights_kernel(const float* __restrict__ W, const float* __restrict__ z)
{
    const int c = blockIdx.x;
    const int tid = threadIdx.x;

    if (c >= CCLS) {
        *reinterpret_cast<uint4*>(g_Wnh + (size_t)c * DDIM + tid * 8) = make_uint4(0u, 0u, 0u, 0u);
        return;
    }

    float acc[8];
#pragma unroll
    for (int j = 0; j < 8; j++) acc[j] = 0.f;

    const int m = g_mcnt[c];
    const int base = c * CAP;
    for (int i = 0; i < m; i++) {
        const int n = g_list[base + i];
        const float v = g_invn[n];
        const float* row = (n < CCLS) ? (W + (size_t)n * DDIM) : (z + (size_t)(n - CCLS) * DDIM);
        const float4* rp = reinterpret_cast<const float4*>(row + tid * 8);
        float4 a = rp[0], b = rp[1];
        acc[0] += v * a.x; acc[1] += v * a.y; acc[2] += v * a.z; acc[3] += v * a.w;
        acc[4] += v * b.x; acc[5] += v * b.y; acc[6] += v * b.z; acc[7] += v * b.w;
    }

    float ssq = 0.f;
#pragma unroll
    for (int j = 0; j < 8; j++) ssq += acc[j] * acc[j];
    __shared__ float sh[256];
    sh[tid] = ssq;
    __syncthreads();
    for (int s = 128; s > 0; s >>= 1) {
        if (tid < s) sh[tid] += sh[tid + s];
        __syncthreads();
    }
    __shared__ float s_scale;
    if (tid == 0) s_scale = 1.f / fmaxf(sqrtf(sh[0]), 1e-12f);
    __syncthreads();
    const float sc = s_scale;

    __half h[8];
#pragma unroll
    for (int j = 0; j < 8; j++) h[j] = __float2half_rn(acc[j] * sc);
    *reinterpret_cast<uint4*>(g_Wnh + (size_t)c * DDIM + tid * 8) = *reinterpret_cast<uint4*>(h);
}

// ---------------- launch ----------------
extern "C" void kernel_launch(void* const* d_in, const int* in_sizes, int n_in,
                              void* d_out, int out_size)
{
    const float* z  = (const float*)d_in[0];   // [4096, 2048]
    const float* W  = (const float*)d_in[1];   // [1000, 2048]
    const int*   pK = (const int*)d_in[2];     // filter_K
    float* out = (float*)d_out;                // [4096, 1000]

    static bool attr_done = false;
    if (!attr_done) {
        cudaFuncSetAttribute(mma_gemm_kernel, cudaFuncAttributeMaxDynamicSharedMemorySize, SMEM_TOTAL);
        attr_done = true;
    }

    void* pP = nullptr;    cudaGetSymbolAddress(&pP, g_P);
    void* pP2 = nullptr;   cudaGetSymbolAddress(&pP2, g_P2);
    void* pSh = nullptr;   cudaGetSymbolAddress(&pSh, g_Sh);
    void* pWnh = nullptr;  cudaGetSymbolAddress(&pWnh, g_Wnh);
    void* pCnt = nullptr;  cudaGetSymbolAddress(&pCnt, g_mcnt);

    const __half* Sh = (const __half*)pSh;

    // 1) zero class counts; fp32 -> fp16 supports [W; z] (padded) + row inverse norms
    cudaMemsetAsync(pCnt, 0, CCLS * sizeof(int));
    cvt_kernel<<<NPAD, 256>>>(W, z);

    // 2) P ~= [W; z] @ W^T  (single fp16 HMMA, split-K=2), [5096, 1000]
    {
        dim3 grid((CCLS + BN - 1) / BN, NPAD / BM, 2);   // 16 x 40 x 2
        mma_gemm_kernel<<<grid, 256, SMEM_TOTAL>>>(Sh, Sh, (float*)pP, (float*)pP2,
                                                   NSUP, (DDIM / BK) / 2);
    }
    // 3) entropy (approx) + exact-repaired argmax + fused class scatter
    ent_argmax_fix_kernel<<<NSUP, 256>>>(W, z);
    // 4) per-class deterministic sort + exact top-K
    sortsel_kernel<<<CCLS, 32>>>(pK);
    // 5) normalized class prototypes -> fp16 (padded rows zeroed)
    class_weights_kernel<<<BNPAD, 256>>>(W, z);
    // 6) out = z @ Wn^T  (single fp16 HMMA), [4096, 1000]
    {
        dim3 grid((CCLS + BN - 1) / BN, BATCH / BM, 1);  // 16 x 32
        mma_gemm_kernel<<<grid, 256, SMEM_TOTAL>>>(Sh + (size_t)CCLS * DDIM,
                                                   (const __half*)pWnh,
                                                   out, out,
                                                   BATCH, DDIM / BK);
    }
}